// round 7
// baseline (speedup 1.0000x reference)
#include <cuda_runtime.h>
#include <cstdint>

#define HNUM 12
#define DHEAD 64
#define BATCH 4
#define LQ 512
#define LK 512
#define DMODEL 768

// ---------------- scratch (device globals; no runtime alloc) ----------------
__device__ float g_Q[BATCH*HNUM*LQ*DHEAD];
__device__ float g_K[BATCH*HNUM*LK*DHEAD];
__device__ float g_V[BATCH*HNUM*LK*DHEAD];
__device__ float g_P[(size_t)BATCH*HNUM*LQ*LK];
__device__ float g_PW[BATCH*HNUM*LQ*4];
__device__ uint32_t g_arc8[BATCH*512*512/4];
__device__ float g_lnk[3*DHEAD];
__device__ float g_lnv[3*DHEAD];

__device__ __forceinline__ float tf32_rna(float x) {
    uint32_t r;
    asm("cvt.rna.tf32.f32 %0, %1;" : "=r"(r) : "f"(x));
    return __uint_as_float(r);
}

#define MMA_TF32(d, a, b)                                                     \
    asm volatile("mma.sync.aligned.m16n8k8.row.col.f32.tf32.tf32.f32 "         \
        "{%0,%1,%2,%3}, {%4,%5,%6,%7}, {%8,%9}, {%0,%1,%2,%3};"                \
        : "+f"((d)[0]), "+f"((d)[1]), "+f"((d)[2]), "+f"((d)[3])               \
        : "r"(__float_as_uint((a)[0])), "r"(__float_as_uint((a)[1])),          \
          "r"(__float_as_uint((a)[2])), "r"(__float_as_uint((a)[3])),          \
          "r"(__float_as_uint((b)[0])), "r"(__float_as_uint((b)[1])))

#define CP_ASYNC16(dst, src) \
    asm volatile("cp.async.cg.shared.global [%0], [%1], 16;" :: "r"(dst), "l"(src) : "memory")
#define CP_COMMIT() asm volatile("cp.async.commit_group;" ::: "memory")
#define CP_WAIT1()  asm volatile("cp.async.wait_group 1;" ::: "memory")
#define CP_WAIT0()  asm volatile("cp.async.wait_group 0;" ::: "memory")

// ---------------- K1: layernorm the 3+3 relation embedding rows -------------
__global__ void ln_prep_kernel(const float* __restrict__ dpk, const float* __restrict__ dpv,
                               const float* __restrict__ kg, const float* __restrict__ kb,
                               const float* __restrict__ vg, const float* __restrict__ vb) {
    int w = threadIdx.x >> 5;
    int lane = threadIdx.x & 31;
    if (w >= 6) return;
    const float* src = (w < 3) ? dpk + w * DHEAD : dpv + (w - 3) * DHEAD;
    const float* g   = (w < 3) ? kg : vg;
    const float* be  = (w < 3) ? kb : vb;
    float* dst       = (w < 3) ? g_lnk + w * DHEAD : g_lnv + (w - 3) * DHEAD;
    float e0 = src[lane], e1 = src[lane + 32];
    float s = e0 + e1;
    #pragma unroll
    for (int o = 16; o; o >>= 1) s += __shfl_xor_sync(0xffffffffu, s, o);
    float mu = s * (1.0f / 64.0f);
    float d0 = e0 - mu, d1 = e1 - mu;
    float v = d0 * d0 + d1 * d1;
    #pragma unroll
    for (int o = 16; o; o >>= 1) v += __shfl_xor_sync(0xffffffffu, v, o);
    float rs = rsqrtf(v * (1.0f / 64.0f) + 1e-5f);
    dst[lane]      = d0 * rs * g[lane]      + be[lane];
    dst[lane + 32] = d1 * rs * g[lane + 32] + be[lane + 32];
}

// ---------------- K1b: pack arc int32 -> uint8 -------------------------------
__global__ __launch_bounds__(256) void arc_pack_kernel(const int* __restrict__ arc) {
    int i = blockIdx.x * 256 + threadIdx.x;
    const int4 a = *(const int4*)&arc[i * 4];
    g_arc8[i] = (uint32_t)a.x | ((uint32_t)a.y << 8) |
                ((uint32_t)a.z << 16) | ((uint32_t)a.w << 24);
}

// ---------------- K2: tf32(rna) mma.sync QKV GEMM ----------------------------
#define A_STRIDE 36
#define B_STRIDE 132
#define STAGE_FLOATS (128 * A_STRIDE + 32 * B_STRIDE)
#define GEMM_SMEM_BYTES (2 * STAGE_FLOATS * 4)

__global__ __launch_bounds__(256, 2) void qkv_gemm_mma_kernel(
    const float* __restrict__ hidden, const float* __restrict__ ctx,
    const float* __restrict__ Wq, const float* __restrict__ bq,
    const float* __restrict__ Wk, const float* __restrict__ bk,
    const float* __restrict__ Wv, const float* __restrict__ bv) {
    extern __shared__ float smem[];

    int sel = blockIdx.z;
    const float* X    = (sel == 0) ? hidden : ctx;
    const float* W    = (sel == 0) ? Wq : (sel == 1 ? Wk : Wv);
    const float* bias = (sel == 0) ? bq : (sel == 1 ? bk : bv);
    float* Out        = (sel == 0) ? g_Q : (sel == 1 ? g_K : g_V);

    int m0 = blockIdx.x * 128;
    int n0 = blockIdx.y * 128;
    int t = threadIdx.x;
    int w = t >> 5;
    int lane = t & 31;
    int gid = lane >> 2;
    int tid4 = lane & 3;
    int wm = w >> 2;
    int wn = w & 3;

    auto load_chunk = [&](int c, int s) {
        int k0 = c * 32;
        float* sA = smem + s * STAGE_FLOATS;
        float* sB = sA + 128 * A_STRIDE;
        #pragma unroll
        for (int it = 0; it < 4; it++) {
            int idx = it * 256 + t;
            int r = idx >> 3, c4 = (idx & 7) << 2;
            uint32_t dst = (uint32_t)__cvta_generic_to_shared(&sA[r * A_STRIDE + c4]);
            CP_ASYNC16(dst, &X[(size_t)(m0 + r) * DMODEL + k0 + c4]);
        }
        #pragma unroll
        for (int it = 0; it < 4; it++) {
            int idx = it * 256 + t;
            int kr = idx >> 5, c4 = (idx & 31) << 2;
            uint32_t dst = (uint32_t)__cvta_generic_to_shared(&sB[kr * B_STRIDE + c4]);
            CP_ASYNC16(dst, &W[(size_t)(k0 + kr) * DMODEL + n0 + c4]);
        }
        CP_COMMIT();
    };

    float acc[4][4][4];
    #pragma unroll
    for (int mt = 0; mt < 4; mt++)
        #pragma unroll
        for (int nt = 0; nt < 4; nt++)
            #pragma unroll
            for (int f = 0; f < 4; f++) acc[mt][nt][f] = 0.f;

    load_chunk(0, 0);
    load_chunk(1, 1);
    CP_WAIT1();
    __syncthreads();

    for (int c = 0; c < 24; c++) {
        int s = c & 1;
        const float* sA = smem + s * STAGE_FLOATS;
        const float* sB = sA + 128 * A_STRIDE;
        #pragma unroll
        for (int ks = 0; ks < 4; ks++) {
            int k = ks * 8 + tid4;
            float afr[4][4];
            #pragma unroll
            for (int mt = 0; mt < 4; mt++) {
                int r = wm * 64 + mt * 16 + gid;
                afr[mt][0] = tf32_rna(sA[r * A_STRIDE + k]);
                afr[mt][1] = tf32_rna(sA[(r + 8) * A_STRIDE + k]);
                afr[mt][2] = tf32_rna(sA[r * A_STRIDE + k + 4]);
                afr[mt][3] = tf32_rna(sA[(r + 8) * A_STRIDE + k + 4]);
            }
            #pragma unroll
            for (int nt = 0; nt < 4; nt++) {
                int n = wn * 32 + nt * 8 + gid;
                float bfr[2];
                bfr[0] = tf32_rna(sB[k * B_STRIDE + n]);
                bfr[1] = tf32_rna(sB[(k + 4) * B_STRIDE + n]);
                #pragma unroll
                for (int mt = 0; mt < 4; mt++)
                    MMA_TF32(acc[mt][nt], afr[mt], bfr);
            }
        }
        __syncthreads();
        if (c + 2 < 24) {
            load_chunk(c + 2, s);
            CP_WAIT1();
        } else {
            CP_WAIT0();
        }
        __syncthreads();
    }

    float bv2[4][2];
    #pragma unroll
    for (int nt = 0; nt < 4; nt++) {
        int col = n0 + wn * 32 + nt * 8 + tid4 * 2;
        bv2[nt][0] = bias[col];
        bv2[nt][1] = bias[col + 1];
    }
    #pragma unroll
    for (int mt = 0; mt < 4; mt++) {
        #pragma unroll
        for (int half = 0; half < 2; half++) {
            int row = m0 + wm * 64 + mt * 16 + gid + half * 8;
            int b = row >> 9, tok = row & 511;
            #pragma unroll
            for (int nt = 0; nt < 4; nt++) {
                int col = n0 + wn * 32 + nt * 8 + tid4 * 2;
                int head = col >> 6, dh = col & 63;
                float2 v;
                v.x = acc[mt][nt][half * 2 + 0] + bv2[nt][0];
                v.y = acc[mt][nt][half * 2 + 1] + bv2[nt][1];
                *(float2*)&Out[((size_t)(b * HNUM + head) * 512 + tok) * 64 + dh] = v;
            }
        }
    }
}

// ---------------- KA: fused QK^T + softmax -> normalized P -------------------
// grid (16 q-tiles of 32, 48 bh), 256 threads.
// Warp w privately owns keys [w*64, w*64+64) for ALL 32 query rows.
// Full 512-key score row lives in CTA registers; only P hits gmem.
#define KSLICE 68
#define FS_Q     0
#define FS_K     (FS_Q + 32*68)                 // 8 slices of 64*68
#define FS_MASK  (FS_K + 8*64*KSLICE)
#define FS_QDP   (FS_MASK + 512)
#define FS_RED   (FS_QDP + 128)                 // 32 rows x 8 warps (max)
#define FS_SUM   (FS_RED + 256)                 // 32 rows x 8 warps x 4
#define FS_FLOATS (FS_SUM + 1024)
#define FS_SMEM_BYTES (FS_FLOATS*4 + 32*512)    // + arc bytes [8 warps][32][64]

__global__ __launch_bounds__(256, 1) void qk_softmax_kernel(const float* __restrict__ mask) {
    extern __shared__ float sm[];
    float* sQ   = sm + FS_Q;
    float* sMask= sm + FS_MASK;
    float* sQdp = sm + FS_QDP;
    float* sRed = sm + FS_RED;
    float* sSum = sm + FS_SUM;
    unsigned char* sArcAll = (unsigned char*)(sm + FS_FLOATS);

    int bh = blockIdx.y;
    int b = bh / HNUM;
    int q0 = blockIdx.x * 32;
    int t = threadIdx.x;
    int w = t >> 5;
    int lane = t & 31;
    int gid = lane >> 2;
    int tid4 = lane & 3;

    float* sKw = sm + FS_K + w * 64 * KSLICE;
    unsigned char* sArcw = sArcAll + w * 2048;   // [32 rows][64 cols]

    const float* Qbase = g_Q + ((size_t)bh * 512 + q0) * 64;
    const float* Kbase = g_K + ((size_t)bh * 512 + w * 64) * 64;
    const char*  Abase = (const char*)g_arc8 + ((size_t)(b * 512 + q0)) * 512 + w * 64;

    // per-warp async loads: K half1 | K half2 + arc (per-thread group semantics)
    #pragma unroll
    for (int i = 0; i < 16; i++) {
        int idx = i * 32 + lane;
        int r = idx >> 4, c4 = (idx & 15) << 2;
        uint32_t dst = (uint32_t)__cvta_generic_to_shared(&sKw[r * KSLICE + c4]);
        CP_ASYNC16(dst, &Kbase[(size_t)r * 64 + c4]);
    }
    CP_COMMIT();
    #pragma unroll
    for (int i = 0; i < 16; i++) {
        int idx = i * 32 + lane;
        int r = 32 + (idx >> 4), c4 = (idx & 15) << 2;
        uint32_t dst = (uint32_t)__cvta_generic_to_shared(&sKw[r * KSLICE + c4]);
        CP_ASYNC16(dst, &Kbase[(size_t)r * 64 + c4]);
    }
    #pragma unroll
    for (int i = 0; i < 4; i++) {
        int idx = i * 32 + lane;
        int r = idx >> 2, c16 = (idx & 3) * 16;
        uint32_t dst = (uint32_t)__cvta_generic_to_shared(&sArcw[r * 64 + c16]);
        CP_ASYNC16(dst, Abase + (size_t)r * 512 + c16);
    }
    CP_COMMIT();

    // cooperative Q (tf32-rounded) + mask
    for (int i = t; i < 32 * 16; i += 256) {
        int r = i >> 4, c4 = (i & 15) << 2;
        float4 v = *(const float4*)&Qbase[r * 64 + c4];
        sQ[r * 68 + c4 + 0] = tf32_rna(v.x);
        sQ[r * 68 + c4 + 1] = tf32_rna(v.y);
        sQ[r * 68 + c4 + 2] = tf32_rna(v.z);
        sQ[r * 68 + c4 + 3] = tf32_rna(v.w);
    }
    for (int i = t; i < 512; i += 256) sMask[i] = mask[b * 512 + i];
    __syncthreads();

    // qdp: warp w computes rows 4w..4w+3
    #pragma unroll
    for (int ri = 0; ri < 4; ri++) {
        int row = w * 4 + ri;
        float q0v = sQ[row * 68 + lane], q1v = sQ[row * 68 + lane + 32];
        float s0 = q0v * g_lnk[lane]       + q1v * g_lnk[lane + 32];
        float s1 = q0v * g_lnk[64 + lane]  + q1v * g_lnk[96 + lane];
        float s2 = q0v * g_lnk[128 + lane] + q1v * g_lnk[160 + lane];
        #pragma unroll
        for (int o = 16; o; o >>= 1) {
            s0 += __shfl_xor_sync(0xffffffffu, s0, o);
            s1 += __shfl_xor_sync(0xffffffffu, s1, o);
            s2 += __shfl_xor_sync(0xffffffffu, s2, o);
        }
        if (lane == 0) {
            sQdp[row * 4 + 0] = s0; sQdp[row * 4 + 1] = s1;
            sQdp[row * 4 + 2] = s2; sQdp[row * 4 + 3] = 0.f;
        }
    }
    __syncthreads();

    // ---- MMA: 32 rows x warp's 64 keys; acc[mt][nt][f] ----
    float acc[2][8][4];
    #pragma unroll
    for (int mt = 0; mt < 2; mt++)
        #pragma unroll
        for (int nt = 0; nt < 8; nt++)
            #pragma unroll
            for (int f = 0; f < 4; f++) acc[mt][nt][f] = 0.f;

    CP_WAIT1();   // K half1 ready
    #pragma unroll
    for (int ks = 0; ks < 8; ks++) {
        int k = ks * 8 + tid4;
        float afr[2][4];
        #pragma unroll
        for (int mt = 0; mt < 2; mt++) {
            int r = mt * 16 + gid;
            afr[mt][0] = sQ[r * 68 + k];
            afr[mt][1] = sQ[(r + 8) * 68 + k];
            afr[mt][2] = sQ[r * 68 + k + 4];
            afr[mt][3] = sQ[(r + 8) * 68 + k + 4];
        }
        #pragma unroll
        for (int nt = 0; nt < 4; nt++) {
            int n = nt * 8 + gid;
            float bfr[2];
            bfr[0] = tf32_rna(sKw[n * KSLICE + k]);
            bfr[1] = tf32_rna(sKw[n * KSLICE + k + 4]);
            #pragma unroll
            for (int mt = 0; mt < 2; mt++)
                MMA_TF32(acc[mt][nt], afr[mt], bfr);
        }
    }
    CP_WAIT0();   // K half2 + arc ready
    #pragma unroll
    for (int ks = 0; ks < 8; ks++) {
        int k = ks * 8 + tid4;
        float afr[2][4];
        #pragma unroll
        for (int mt = 0; mt < 2; mt++) {
            int r = mt * 16 + gid;
            afr[mt][0] = sQ[r * 68 + k];
            afr[mt][1] = sQ[(r + 8) * 68 + k];
            afr[mt][2] = sQ[r * 68 + k + 4];
            afr[mt][3] = sQ[(r + 8) * 68 + k + 4];
        }
        #pragma unroll
        for (int nt = 4; nt < 8; nt++) {
            int n = nt * 8 + gid;
            float bfr[2];
            bfr[0] = tf32_rna(sKw[n * KSLICE + k]);
            bfr[1] = tf32_rna(sKw[n * KSLICE + k + 4]);
            #pragma unroll
            for (int mt = 0; mt < 2; mt++)
                MMA_TF32(acc[mt][nt], afr[mt], bfr);
        }
    }

    // ---- transform: acc = acc*0.125 + qdp[arc] + mask; thread-local row max ----
    float mx[2][2];
    #pragma unroll
    for (int mt = 0; mt < 2; mt++) {
        #pragma unroll
        for (int h = 0; h < 2; h++) {
            int row = mt * 16 + h * 8 + gid;
            float m = -1e30f;
            #pragma unroll
            for (int nt = 0; nt < 8; nt++) {
                int col = nt * 8 + tid4 * 2;
                int a0 = sArcw[row * 64 + col];
                int a1 = sArcw[row * 64 + col + 1];
                float x0 = acc[mt][nt][h*2+0] * 0.125f + sQdp[row*4 + a0] + sMask[w*64 + col];
                float x1 = acc[mt][nt][h*2+1] * 0.125f + sQdp[row*4 + a1] + sMask[w*64 + col + 1];
                acc[mt][nt][h*2+0] = x0;
                acc[mt][nt][h*2+1] = x1;
                m = fmaxf(m, fmaxf(x0, x1));
            }
            m = fmaxf(m, __shfl_xor_sync(0xffffffffu, m, 1));
            m = fmaxf(m, __shfl_xor_sync(0xffffffffu, m, 2));
            mx[mt][h] = m;
            if (tid4 == 0) sRed[row * 8 + w] = m;
        }
    }
    __syncthreads();

    // ---- global row max; exp; partial sums ----
    #pragma unroll
    for (int mt = 0; mt < 2; mt++) {
        #pragma unroll
        for (int h = 0; h < 2; h++) {
            int row = mt * 16 + h * 8 + gid;
            float m = sRed[row * 8 + 0];
            #pragma unroll
            for (int j = 1; j < 8; j++) m = fmaxf(m, sRed[row * 8 + j]);
            float sum = 0.f, p0 = 0.f, p1 = 0.f, p2 = 0.f;
            #pragma unroll
            for (int nt = 0; nt < 8; nt++) {
                int col = nt * 8 + tid4 * 2;
                int a0 = sArcw[row * 64 + col];
                int a1 = sArcw[row * 64 + col + 1];
                float px = __expf(acc[mt][nt][h*2+0] - m);
                float py = __expf(acc[mt][nt][h*2+1] - m);
                acc[mt][nt][h*2+0] = px;
                acc[mt][nt][h*2+1] = py;
                sum += px + py;
                p0 += (a0 == 0 ? px : 0.f) + (a1 == 0 ? py : 0.f);
                p1 += (a0 == 1 ? px : 0.f) + (a1 == 1 ? py : 0.f);
                p2 += (a0 == 2 ? px : 0.f) + (a1 == 2 ? py : 0.f);
            }
            #pragma unroll
            for (int o = 2; o; o >>= 1) {
                sum += __shfl_xor_sync(0xffffffffu, sum, o);
                p0  += __shfl_xor_sync(0xffffffffu, p0, o);
                p1  += __shfl_xor_sync(0xffffffffu, p1, o);
                p2  += __shfl_xor_sync(0xffffffffu, p2, o);
            }
            if (tid4 == 0) {
                float* dst = &sSum[(row * 8 + w) * 4];
                dst[0] = sum; dst[1] = p0; dst[2] = p1; dst[3] = p2;
            }
        }
    }
    __syncthreads();

    // ---- combine; normalize; write P (and PW from warp 0) ----
    #pragma unroll
    for (int mt = 0; mt < 2; mt++) {
        #pragma unroll
        for (int h = 0; h < 2; h++) {
            int row = mt * 16 + h * 8 + gid;
            float sum = 0.f, p0 = 0.f, p1 = 0.f, p2 = 0.f;
            #pragma unroll
            for (int j = 0; j < 8; j++) {
                const float* src = &sSum[(row * 8 + j) * 4];
                sum += src[0]; p0 += src[1]; p1 += src[2]; p2 += src[3];
            }
            float inv = 1.f / sum;
            float* Prow = g_P + ((size_t)bh * 512 + q0 + row) * 512 + w * 64;
            #pragma unroll
            for (int nt = 0; nt < 8; nt++) {
                float2 pv;
                pv.x = tf32_rna(acc[mt][nt][h*2+0] * inv);
                pv.y = tf32_rna(acc[mt][nt][h*2+1] * inv);
                *(float2*)&Prow[nt * 8 + tid4 * 2] = pv;
            }
            if (w == 0 && tid4 == 0) {
                float4 pwv = make_float4(p0 * inv, p1 * inv, p2 * inv, 0.f);
                *(float4*)&g_PW[((size_t)bh * 512 + q0 + row) * 4] = pwv;
            }
        }
    }
}

// ---------------- KC: O = P V + pw . lnv -------------------------------------
#define P_STRIDE 36
#define V_STRIDE 72
#define PV_STAGE (64 * P_STRIDE + 32 * V_STRIDE)
#define PV_SMEM_BYTES (2 * PV_STAGE * 4)

__global__ __launch_bounds__(256, 2) void pv_kernel(float* __restrict__ out) {
    extern __shared__ float sm[];

    int bh = blockIdx.y;
    int b = bh / HNUM, h = bh % HNUM;
    int q0 = blockIdx.x * 64;
    int t = threadIdx.x;
    int w = t >> 5;
    int lane = t & 31;
    int gid = lane >> 2;
    int tid4 = lane & 3;
    int wm = w >> 1;
    int wn = w & 1;

    const float* Pbase = g_P + ((size_t)bh * 512 + q0) * 512;
    const float* Vbase = g_V + (size_t)bh * 512 * 64;

    auto load_chunk = [&](int c, int s) {
        int k0 = c * 32;
        float* sP = sm + s * PV_STAGE;
        float* sV = sP + 64 * P_STRIDE;
        #pragma unroll
        for (int it = 0; it < 2; it++) {
            int idx = it * 256 + t;
            int r = idx >> 3, c4 = (idx & 7) << 2;
            uint32_t dst = (uint32_t)__cvta_generic_to_shared(&sP[r * P_STRIDE + c4]);
            CP_ASYNC16(dst, &Pbase[(size_t)r * 512 + k0 + c4]);
        }
        #pragma unroll
        for (int it = 0; it < 2; it++) {
            int idx = it * 256 + t;
            int r = idx >> 4, c4 = (idx & 15) << 2;
            uint32_t dst = (uint32_t)__cvta_generic_to_shared(&sV[r * V_STRIDE + c4]);
            CP_ASYNC16(dst, &Vbase[(size_t)(k0 + r) * 64 + c4]);
        }
        CP_COMMIT();
    };

    float acc[4][4];
    #pragma unroll
    for (int nt = 0; nt < 4; nt++)
        #pragma unroll
        for (int f = 0; f < 4; f++) acc[nt][f] = 0.f;

    load_chunk(0, 0);
    load_chunk(1, 1);
    CP_WAIT1();
    __syncthreads();

    for (int c = 0; c < 16; c++) {
        int s = c & 1;
        const float* sP = sm + s * PV_STAGE;
        const float* sV = sP + 64 * P_STRIDE;
        #pragma unroll
        for (int ks = 0; ks < 4; ks++) {
            int k = ks * 8 + tid4;
            float afr[4];
            int r = wm * 16 + gid;
            afr[0] = sP[r * P_STRIDE + k];
            afr[1] = sP[(r + 8) * P_STRIDE + k];
            afr[2] = sP[r * P_STRIDE + k + 4];
            afr[3] = sP[(r + 8) * P_STRIDE + k + 4];
            #pragma unroll
            for (int nt = 0; nt < 4; nt++) {
                int n = wn * 32 + nt * 8 + gid;
                float bfr[2];
                bfr[0] = tf32_rna(sV[k * V_STRIDE + n]);
                bfr[1] = tf32_rna(sV[(k + 4) * V_STRIDE + n]);
                MMA_TF32(acc[nt], afr, bfr);
            }
        }
        __syncthreads();
        if (c + 2 < 16) {
            load_chunk(c + 2, s);
            CP_WAIT1();
        } else {
            CP_WAIT0();
        }
        __syncthreads();
    }

    int r0 = wm * 16 + gid, r1 = r0 + 8;
    float4 pw0 = *(float4*)&g_PW[((size_t)bh * 512 + q0 + r0) * 4];
    float4 pw1 = *(float4*)&g_PW[((size_t)bh * 512 + q0 + r1) * 4];
    #pragma unroll
    for (int nt = 0; nt < 4; nt++) {
        int col = wn * 32 + nt * 8 + tid4 * 2;
        float l0a = g_lnv[col],       l0b = g_lnv[col + 1];
        float l1a = g_lnv[64 + col],  l1b = g_lnv[64 + col + 1];
        float l2a = g_lnv[128 + col], l2b = g_lnv[128 + col + 1];
        float2 v0, v1;
        v0.x = acc[nt][0] + pw0.x * l0a + pw0.y * l1a + pw0.z * l2a;
        v0.y = acc[nt][1] + pw0.x * l0b + pw0.y * l1b + pw0.z * l2b;
        v1.x = acc[nt][2] + pw1.x * l0a + pw1.y * l1a + pw1.z * l2a;
        v1.y = acc[nt][3] + pw1.x * l0b + pw1.y * l1b + pw1.z * l2b;
        *(float2*)&out[(size_t)(b * 512 + q0 + r0) * 768 + h * 64 + col] = v0;
        *(float2*)&out[(size_t)(b * 512 + q0 + r1) * 768 + h * 64 + col] = v1;
    }
}

// ---------------- launcher ----------------------------------------------------
extern "C" void kernel_launch(void* const* d_in, const int* in_sizes, int n_in,
                              void* d_out, int out_size) {
    const float* hidden = (const float*)d_in[0];
    const float* ctx    = (const float*)d_in[1];
    const float* mask   = (const float*)d_in[2];
    const int*   arc    = (const int*)d_in[3];
    const float* Wq = (const float*)d_in[4];  const float* bq = (const float*)d_in[5];
    const float* Wk = (const float*)d_in[6];  const float* bk = (const float*)d_in[7];
    const float* Wv = (const float*)d_in[8];  const float* bv = (const float*)d_in[9];
    const float* dpk = (const float*)d_in[10]; const float* dpv = (const float*)d_in[11];
    const float* lkg = (const float*)d_in[12]; const float* lkb = (const float*)d_in[13];
    const float* lvg = (const float*)d_in[14]; const float* lvb = (const float*)d_in[15];
    float* out = (float*)d_out;

    ln_prep_kernel<<<1, 192>>>(dpk, dpv, lkg, lkb, lvg, lvb);
    arc_pack_kernel<<<1024, 256>>>(arc);

    cudaFuncSetAttribute(qkv_gemm_mma_kernel, cudaFuncAttributeMaxDynamicSharedMemorySize,
                         GEMM_SMEM_BYTES);
    qkv_gemm_mma_kernel<<<dim3(16, 6, 3), 256, GEMM_SMEM_BYTES>>>(
        hidden, ctx, Wq, bq, Wk, bk, Wv, bv);

    cudaFuncSetAttribute(qk_softmax_kernel, cudaFuncAttributeMaxDynamicSharedMemorySize,
                         FS_SMEM_BYTES);
    qk_softmax_kernel<<<dim3(16, 48), 256, FS_SMEM_BYTES>>>(mask);

    cudaFuncSetAttribute(pv_kernel, cudaFuncAttributeMaxDynamicSharedMemorySize,
                         PV_SMEM_BYTES);
    pv_kernel<<<dim3(8, 48), 256, PV_SMEM_BYTES>>>(out);
}

// round 8
// speedup vs baseline: 1.1265x; 1.1265x over previous
#include <cuda_runtime.h>
#include <cstdint>

#define HNUM 12
#define DHEAD 64
#define BATCH 4
#define LQ 512
#define LK 512
#define DMODEL 768

// ---------------- scratch (device globals; no runtime alloc) ----------------
__device__ float g_Q[BATCH*HNUM*LQ*DHEAD];
__device__ float g_K[BATCH*HNUM*LK*DHEAD];
__device__ float g_V[BATCH*HNUM*LK*DHEAD];
__device__ float g_S[(size_t)BATCH*HNUM*LQ*LK];
__device__ float g_P[(size_t)BATCH*HNUM*LQ*LK];
__device__ float g_PW[BATCH*HNUM*LQ*4];
__device__ uint32_t g_arc8[BATCH*512*512/4];
__device__ float g_lnk[3*DHEAD];
__device__ float g_lnv[3*DHEAD];

__device__ __forceinline__ float tf32_rna(float x) {
    uint32_t r;
    asm("cvt.rna.tf32.f32 %0, %1;" : "=r"(r) : "f"(x));
    return __uint_as_float(r);
}

#define MMA_TF32(d, a, b)                                                     \
    asm volatile("mma.sync.aligned.m16n8k8.row.col.f32.tf32.tf32.f32 "         \
        "{%0,%1,%2,%3}, {%4,%5,%6,%7}, {%8,%9}, {%0,%1,%2,%3};"                \
        : "+f"((d)[0]), "+f"((d)[1]), "+f"((d)[2]), "+f"((d)[3])               \
        : "r"(__float_as_uint((a)[0])), "r"(__float_as_uint((a)[1])),          \
          "r"(__float_as_uint((a)[2])), "r"(__float_as_uint((a)[3])),          \
          "r"(__float_as_uint((b)[0])), "r"(__float_as_uint((b)[1])))

#define CP_ASYNC16(dst, src) \
    asm volatile("cp.async.cg.shared.global [%0], [%1], 16;" :: "r"(dst), "l"(src) : "memory")
#define CP_COMMIT() asm volatile("cp.async.commit_group;" ::: "memory")
#define CP_WAIT1()  asm volatile("cp.async.wait_group 1;" ::: "memory")
#define CP_WAIT0()  asm volatile("cp.async.wait_group 0;" ::: "memory")

// ---------------- K1: arc pack (blocks 0..1023) + LN prep (block 1024) ------
__global__ __launch_bounds__(256) void prep_kernel(
    const int* __restrict__ arc,
    const float* __restrict__ dpk, const float* __restrict__ dpv,
    const float* __restrict__ kg, const float* __restrict__ kb,
    const float* __restrict__ vg, const float* __restrict__ vb) {
    if (blockIdx.x < 1024) {
        int i = blockIdx.x * 256 + threadIdx.x;
        const int4 a = *(const int4*)&arc[i * 4];
        g_arc8[i] = (uint32_t)a.x | ((uint32_t)a.y << 8) |
                    ((uint32_t)a.z << 16) | ((uint32_t)a.w << 24);
        return;
    }
    int w = threadIdx.x >> 5;
    int lane = threadIdx.x & 31;
    if (w >= 6) return;
    const float* src = (w < 3) ? dpk + w * DHEAD : dpv + (w - 3) * DHEAD;
    const float* g   = (w < 3) ? kg : vg;
    const float* be  = (w < 3) ? kb : vb;
    float* dst       = (w < 3) ? g_lnk + w * DHEAD : g_lnv + (w - 3) * DHEAD;
    float e0 = src[lane], e1 = src[lane + 32];
    float s = e0 + e1;
    #pragma unroll
    for (int o = 16; o; o >>= 1) s += __shfl_xor_sync(0xffffffffu, s, o);
    float mu = s * (1.0f / 64.0f);
    float d0 = e0 - mu, d1 = e1 - mu;
    float v = d0 * d0 + d1 * d1;
    #pragma unroll
    for (int o = 16; o; o >>= 1) v += __shfl_xor_sync(0xffffffffu, v, o);
    float rs = rsqrtf(v * (1.0f / 64.0f) + 1e-5f);
    dst[lane]      = d0 * rs * g[lane]      + be[lane];
    dst[lane + 32] = d1 * rs * g[lane + 32] + be[lane + 32];
}

// ---------------- K2: tf32(rna) mma.sync QKV GEMM ----------------------------
// Outputs are stored ALREADY tf32-rounded (consumers skip cvt).
#define A_STRIDE 36
#define B_STRIDE 132
#define STAGE_FLOATS (128 * A_STRIDE + 32 * B_STRIDE)
#define GEMM_SMEM_BYTES (2 * STAGE_FLOATS * 4)

__global__ __launch_bounds__(256, 2) void qkv_gemm_mma_kernel(
    const float* __restrict__ hidden, const float* __restrict__ ctx,
    const float* __restrict__ Wq, const float* __restrict__ bq,
    const float* __restrict__ Wk, const float* __restrict__ bk,
    const float* __restrict__ Wv, const float* __restrict__ bv) {
    extern __shared__ float smem[];

    int sel = blockIdx.z;
    const float* X    = (sel == 0) ? hidden : ctx;
    const float* W    = (sel == 0) ? Wq : (sel == 1 ? Wk : Wv);
    const float* bias = (sel == 0) ? bq : (sel == 1 ? bk : bv);
    float* Out        = (sel == 0) ? g_Q : (sel == 1 ? g_K : g_V);

    int m0 = blockIdx.x * 128;
    int n0 = blockIdx.y * 128;
    int t = threadIdx.x;
    int w = t >> 5;
    int lane = t & 31;
    int gid = lane >> 2;
    int tid4 = lane & 3;
    int wm = w >> 2;
    int wn = w & 3;

    auto load_chunk = [&](int c, int s) {
        int k0 = c * 32;
        float* sA = smem + s * STAGE_FLOATS;
        float* sB = sA + 128 * A_STRIDE;
        #pragma unroll
        for (int it = 0; it < 4; it++) {
            int idx = it * 256 + t;
            int r = idx >> 3, c4 = (idx & 7) << 2;
            uint32_t dst = (uint32_t)__cvta_generic_to_shared(&sA[r * A_STRIDE + c4]);
            CP_ASYNC16(dst, &X[(size_t)(m0 + r) * DMODEL + k0 + c4]);
        }
        #pragma unroll
        for (int it = 0; it < 4; it++) {
            int idx = it * 256 + t;
            int kr = idx >> 5, c4 = (idx & 31) << 2;
            uint32_t dst = (uint32_t)__cvta_generic_to_shared(&sB[kr * B_STRIDE + c4]);
            CP_ASYNC16(dst, &W[(size_t)(k0 + kr) * DMODEL + n0 + c4]);
        }
        CP_COMMIT();
    };

    float acc[4][4][4];
    #pragma unroll
    for (int mt = 0; mt < 4; mt++)
        #pragma unroll
        for (int nt = 0; nt < 4; nt++)
            #pragma unroll
            for (int f = 0; f < 4; f++) acc[mt][nt][f] = 0.f;

    load_chunk(0, 0);
    load_chunk(1, 1);
    CP_WAIT1();
    __syncthreads();

    for (int c = 0; c < 24; c++) {
        int s = c & 1;
        const float* sA = smem + s * STAGE_FLOATS;
        const float* sB = sA + 128 * A_STRIDE;
        #pragma unroll
        for (int ks = 0; ks < 4; ks++) {
            int k = ks * 8 + tid4;
            float afr[4][4];
            #pragma unroll
            for (int mt = 0; mt < 4; mt++) {
                int r = wm * 64 + mt * 16 + gid;
                afr[mt][0] = tf32_rna(sA[r * A_STRIDE + k]);
                afr[mt][1] = tf32_rna(sA[(r + 8) * A_STRIDE + k]);
                afr[mt][2] = tf32_rna(sA[r * A_STRIDE + k + 4]);
                afr[mt][3] = tf32_rna(sA[(r + 8) * A_STRIDE + k + 4]);
            }
            #pragma unroll
            for (int nt = 0; nt < 4; nt++) {
                int n = wn * 32 + nt * 8 + gid;
                float bfr[2];
                bfr[0] = tf32_rna(sB[k * B_STRIDE + n]);
                bfr[1] = tf32_rna(sB[(k + 4) * B_STRIDE + n]);
                #pragma unroll
                for (int mt = 0; mt < 4; mt++)
                    MMA_TF32(acc[mt][nt], afr[mt], bfr);
            }
        }
        __syncthreads();
        if (c + 2 < 24) {
            load_chunk(c + 2, s);
            CP_WAIT1();
        } else {
            CP_WAIT0();
        }
        __syncthreads();
    }

    float bv2[4][2];
    #pragma unroll
    for (int nt = 0; nt < 4; nt++) {
        int col = n0 + wn * 32 + nt * 8 + tid4 * 2;
        bv2[nt][0] = bias[col];
        bv2[nt][1] = bias[col + 1];
    }
    #pragma unroll
    for (int mt = 0; mt < 4; mt++) {
        #pragma unroll
        for (int half = 0; half < 2; half++) {
            int row = m0 + wm * 64 + mt * 16 + gid + half * 8;
            int b = row >> 9, tok = row & 511;
            #pragma unroll
            for (int nt = 0; nt < 4; nt++) {
                int col = n0 + wn * 32 + nt * 8 + tid4 * 2;
                int head = col >> 6, dh = col & 63;
                float2 v;
                v.x = tf32_rna(acc[mt][nt][half * 2 + 0] + bv2[nt][0]);
                v.y = tf32_rna(acc[mt][nt][half * 2 + 1] + bv2[nt][1]);
                *(float2*)&Out[((size_t)(b * HNUM + head) * 512 + tok) * 64 + dh] = v;
            }
        }
    }
}

// ---------------- KA: S = Q K^T  (inputs pre-rounded) ------------------------
#define QK_STRIDE 68
#define QK_SMEM_BYTES (2 * 128 * QK_STRIDE * 4)   // 69632

__global__ __launch_bounds__(256, 2) void qk_kernel() {
    extern __shared__ float sm[];
    float* sQ = sm;
    float* sK = sm + 128 * QK_STRIDE;

    int bh = blockIdx.z;
    int q0 = blockIdx.x * 128;
    int k0 = blockIdx.y * 128;
    int t = threadIdx.x;
    int w = t >> 5;
    int lane = t & 31;
    int gid = lane >> 2;
    int tid4 = lane & 3;
    int wm = w >> 2;
    int wn = w & 3;

    const float* Qbase = g_Q + ((size_t)bh * 512 + q0) * 64;
    const float* Kbase = g_K + ((size_t)bh * 512 + k0) * 64;

    // async one-shot load of both tiles
    #pragma unroll
    for (int it = 0; it < 8; it++) {
        int idx = it * 256 + t;
        int r = idx >> 4, c4 = (idx & 15) << 2;
        uint32_t dq = (uint32_t)__cvta_generic_to_shared(&sQ[r * QK_STRIDE + c4]);
        CP_ASYNC16(dq, &Qbase[(size_t)r * 64 + c4]);
        uint32_t dk = (uint32_t)__cvta_generic_to_shared(&sK[r * QK_STRIDE + c4]);
        CP_ASYNC16(dk, &Kbase[(size_t)r * 64 + c4]);
    }
    CP_COMMIT();
    CP_WAIT0();
    __syncthreads();

    float acc[4][4][4];
    #pragma unroll
    for (int mt = 0; mt < 4; mt++)
        #pragma unroll
        for (int nt = 0; nt < 4; nt++)
            #pragma unroll
            for (int f = 0; f < 4; f++) acc[mt][nt][f] = 0.f;

    #pragma unroll
    for (int ks = 0; ks < 8; ks++) {
        int k = ks * 8 + tid4;
        float afr[4][4];
        #pragma unroll
        for (int mt = 0; mt < 4; mt++) {
            int r = wm * 64 + mt * 16 + gid;
            afr[mt][0] = sQ[r * QK_STRIDE + k];
            afr[mt][1] = sQ[(r + 8) * QK_STRIDE + k];
            afr[mt][2] = sQ[r * QK_STRIDE + k + 4];
            afr[mt][3] = sQ[(r + 8) * QK_STRIDE + k + 4];
        }
        #pragma unroll
        for (int nt = 0; nt < 4; nt++) {
            int n = wn * 32 + nt * 8 + gid;
            float bfr[2];
            bfr[0] = sK[n * QK_STRIDE + k];
            bfr[1] = sK[n * QK_STRIDE + k + 4];
            #pragma unroll
            for (int mt = 0; mt < 4; mt++)
                MMA_TF32(acc[mt][nt], afr[mt], bfr);
        }
    }

    #pragma unroll
    for (int mt = 0; mt < 4; mt++) {
        #pragma unroll
        for (int half = 0; half < 2; half++) {
            int q = q0 + wm * 64 + mt * 16 + gid + half * 8;
            float* Srow = g_S + ((size_t)bh * 512 + q) * 512;
            #pragma unroll
            for (int nt = 0; nt < 4; nt++) {
                int col = k0 + wn * 32 + nt * 8 + tid4 * 2;
                *(float2*)&Srow[col] =
                    make_float2(acc[mt][nt][half * 2], acc[mt][nt][half * 2 + 1]);
            }
        }
    }
}

// ---------------- KB: row softmax + arc masses, writes normalized P ----------
__global__ __launch_bounds__(256) void softmax_kernel(const float* __restrict__ mask) {
    int bh = blockIdx.y;
    int b = bh / HNUM;
    int q = blockIdx.x * 8 + (threadIdx.x >> 5);
    int lane = threadIdx.x & 31;

    const float* Qrow = g_Q + ((size_t)bh * 512 + q) * 64;
    float q0v = Qrow[lane], q1v = Qrow[lane + 32];
    float s0 = q0v * g_lnk[lane]       + q1v * g_lnk[lane + 32];
    float s1 = q0v * g_lnk[64 + lane]  + q1v * g_lnk[96 + lane];
    float s2 = q0v * g_lnk[128 + lane] + q1v * g_lnk[160 + lane];
    #pragma unroll
    for (int o = 16; o; o >>= 1) {
        s0 += __shfl_xor_sync(0xffffffffu, s0, o);
        s1 += __shfl_xor_sync(0xffffffffu, s1, o);
        s2 += __shfl_xor_sync(0xffffffffu, s2, o);
    }
    float qd[4] = {s0, s1, s2, 0.f};

    const float* Srow = g_S + ((size_t)bh * 512 + q) * 512;
    const uint32_t* arcw = g_arc8 + ((size_t)(b * 512 + q)) * 128 + lane * 4;
    const float* mrow = mask + b * 512 + lane * 16;

    float x[16];
    int a[16];
    #pragma unroll
    for (int j = 0; j < 4; j++) {
        float4 sv = *(const float4*)&Srow[lane * 16 + j * 4];
        float4 mv = *(const float4*)&mrow[j * 4];
        uint32_t aw = arcw[j];
        a[j*4+0] = aw & 3;          a[j*4+1] = (aw >> 8) & 3;
        a[j*4+2] = (aw >> 16) & 3;  a[j*4+3] = (aw >> 24) & 3;
        x[j*4+0] = sv.x * 0.125f + qd[a[j*4+0]] + mv.x;
        x[j*4+1] = sv.y * 0.125f + qd[a[j*4+1]] + mv.y;
        x[j*4+2] = sv.z * 0.125f + qd[a[j*4+2]] + mv.z;
        x[j*4+3] = sv.w * 0.125f + qd[a[j*4+3]] + mv.w;
    }
    float mx = x[0];
    #pragma unroll
    for (int j = 1; j < 16; j++) mx = fmaxf(mx, x[j]);
    #pragma unroll
    for (int o = 16; o; o >>= 1) mx = fmaxf(mx, __shfl_xor_sync(0xffffffffu, mx, o));

    float sum = 0.f, p0 = 0.f, p1 = 0.f, p2 = 0.f;
    #pragma unroll
    for (int j = 0; j < 16; j++) {
        float p = __expf(x[j] - mx);
        x[j] = p;
        sum += p;
        p0 += (a[j] == 0) ? p : 0.f;
        p1 += (a[j] == 1) ? p : 0.f;
        p2 += (a[j] == 2) ? p : 0.f;
    }
    #pragma unroll
    for (int o = 16; o; o >>= 1) {
        sum += __shfl_xor_sync(0xffffffffu, sum, o);
        p0  += __shfl_xor_sync(0xffffffffu, p0, o);
        p1  += __shfl_xor_sync(0xffffffffu, p1, o);
        p2  += __shfl_xor_sync(0xffffffffu, p2, o);
    }
    float inv = 1.f / sum;

    float* Prow = g_P + ((size_t)bh * 512 + q) * 512;
    #pragma unroll
    for (int j = 0; j < 4; j++) {
        float4 pv;
        pv.x = tf32_rna(x[j*4+0] * inv);
        pv.y = tf32_rna(x[j*4+1] * inv);
        pv.z = tf32_rna(x[j*4+2] * inv);
        pv.w = tf32_rna(x[j*4+3] * inv);
        *(float4*)&Prow[lane * 16 + j * 4] = pv;
    }
    if (lane == 0) {
        float4 pwv = make_float4(p0 * inv, p1 * inv, p2 * inv, 0.f);
        *(float4*)&g_PW[((size_t)bh * 512 + q) * 4] = pwv;
    }
}

// ---------------- KC: O = P V + pw . lnv -------------------------------------
#define P_STRIDE 36
#define V_STRIDE 72
#define PV_STAGE (64 * P_STRIDE + 32 * V_STRIDE)
#define PV_SMEM_BYTES (2 * PV_STAGE * 4)

__global__ __launch_bounds__(256, 3) void pv_kernel(float* __restrict__ out) {
    extern __shared__ float sm[];

    int bh = blockIdx.y;
    int b = bh / HNUM, h = bh % HNUM;
    int q0 = blockIdx.x * 64;
    int t = threadIdx.x;
    int w = t >> 5;
    int lane = t & 31;
    int gid = lane >> 2;
    int tid4 = lane & 3;
    int wm = w >> 1;
    int wn = w & 1;

    const float* Pbase = g_P + ((size_t)bh * 512 + q0) * 512;
    const float* Vbase = g_V + (size_t)bh * 512 * 64;

    auto load_chunk = [&](int c, int s) {
        int k0 = c * 32;
        float* sP = sm + s * PV_STAGE;
        float* sV = sP + 64 * P_STRIDE;
        #pragma unroll
        for (int it = 0; it < 2; it++) {
            int idx = it * 256 + t;
            int r = idx >> 3, c4 = (idx & 7) << 2;
            uint32_t dst = (uint32_t)__cvta_generic_to_shared(&sP[r * P_STRIDE + c4]);
            CP_ASYNC16(dst, &Pbase[(size_t)r * 512 + k0 + c4]);
        }
        #pragma unroll
        for (int it = 0; it < 2; it++) {
            int idx = it * 256 + t;
            int r = idx >> 4, c4 = (idx & 15) << 2;
            uint32_t dst = (uint32_t)__cvta_generic_to_shared(&sV[r * V_STRIDE + c4]);
            CP_ASYNC16(dst, &Vbase[(size_t)(k0 + r) * 64 + c4]);
        }
        CP_COMMIT();
    };

    float acc[4][4];
    #pragma unroll
    for (int nt = 0; nt < 4; nt++)
        #pragma unroll
        for (int f = 0; f < 4; f++) acc[nt][f] = 0.f;

    load_chunk(0, 0);
    load_chunk(1, 1);
    CP_WAIT1();
    __syncthreads();

    for (int c = 0; c < 16; c++) {
        int s = c & 1;
        const float* sP = sm + s * PV_STAGE;
        const float* sV = sP + 64 * P_STRIDE;
        #pragma unroll
        for (int ks = 0; ks < 4; ks++) {
            int k = ks * 8 + tid4;
            float afr[4];
            int r = wm * 16 + gid;
            afr[0] = sP[r * P_STRIDE + k];
            afr[1] = sP[(r + 8) * P_STRIDE + k];
            afr[2] = sP[r * P_STRIDE + k + 4];
            afr[3] = sP[(r + 8) * P_STRIDE + k + 4];
            #pragma unroll
            for (int nt = 0; nt < 4; nt++) {
                int n = wn * 32 + nt * 8 + gid;
                float bfr[2];
                bfr[0] = sV[k * V_STRIDE + n];
                bfr[1] = sV[(k + 4) * V_STRIDE + n];
                MMA_TF32(acc[nt], afr, bfr);
            }
        }
        __syncthreads();
        if (c + 2 < 16) {
            load_chunk(c + 2, s);
            CP_WAIT1();
        } else {
            CP_WAIT0();
        }
        __syncthreads();
    }

    int r0 = wm * 16 + gid, r1 = r0 + 8;
    float4 pw0 = *(float4*)&g_PW[((size_t)bh * 512 + q0 + r0) * 4];
    float4 pw1 = *(float4*)&g_PW[((size_t)bh * 512 + q0 + r1) * 4];
    #pragma unroll
    for (int nt = 0; nt < 4; nt++) {
        int col = wn * 32 + nt * 8 + tid4 * 2;
        float l0a = g_lnv[col],       l0b = g_lnv[col + 1];
        float l1a = g_lnv[64 + col],  l1b = g_lnv[64 + col + 1];
        float l2a = g_lnv[128 + col], l2b = g_lnv[128 + col + 1];
        float2 v0, v1;
        v0.x = acc[nt][0] + pw0.x * l0a + pw0.y * l1a + pw0.z * l2a;
        v0.y = acc[nt][1] + pw0.x * l0b + pw0.y * l1b + pw0.z * l2b;
        v1.x = acc[nt][2] + pw1.x * l0a + pw1.y * l1a + pw1.z * l2a;
        v1.y = acc[nt][3] + pw1.x * l0b + pw1.y * l1b + pw1.z * l2b;
        *(float2*)&out[(size_t)(b * 512 + q0 + r0) * 768 + h * 64 + col] = v0;
        *(float2*)&out[(size_t)(b * 512 + q0 + r1) * 768 + h * 64 + col] = v1;
    }
}

// ---------------- launcher ----------------------------------------------------
extern "C" void kernel_launch(void* const* d_in, const int* in_sizes, int n_in,
                              void* d_out, int out_size) {
    const float* hidden = (const float*)d_in[0];
    const float* ctx    = (const float*)d_in[1];
    const float* mask   = (const float*)d_in[2];
    const int*   arc    = (const int*)d_in[3];
    const float* Wq = (const float*)d_in[4];  const float* bq = (const float*)d_in[5];
    const float* Wk = (const float*)d_in[6];  const float* bk = (const float*)d_in[7];
    const float* Wv = (const float*)d_in[8];  const float* bv = (const float*)d_in[9];
    const float* dpk = (const float*)d_in[10]; const float* dpv = (const float*)d_in[11];
    const float* lkg = (const float*)d_in[12]; const float* lkb = (const float*)d_in[13];
    const float* lvg = (const float*)d_in[14]; const float* lvb = (const float*)d_in[15];
    float* out = (float*)d_out;

    prep_kernel<<<1025, 256>>>(arc, dpk, dpv, lkg, lkb, lvg, lvb);

    cudaFuncSetAttribute(qkv_gemm_mma_kernel, cudaFuncAttributeMaxDynamicSharedMemorySize,
                         GEMM_SMEM_BYTES);
    qkv_gemm_mma_kernel<<<dim3(16, 6, 3), 256, GEMM_SMEM_BYTES>>>(
        hidden, ctx, Wq, bq, Wk, bk, Wv, bv);

    cudaFuncSetAttribute(qk_kernel, cudaFuncAttributeMaxDynamicSharedMemorySize,
                         QK_SMEM_BYTES);
    qk_kernel<<<dim3(4, 4, 48), 256, QK_SMEM_BYTES>>>();

    softmax_kernel<<<dim3(64, 48), 256>>>(mask);

    cudaFuncSetAttribute(pv_kernel, cudaFuncAttributeMaxDynamicSharedMemorySize,
                         PV_SMEM_BYTES);
    pv_kernel<<<dim3(8, 48), 256, PV_SMEM_BYTES>>>(out);
}

// round 9
// speedup vs baseline: 1.2396x; 1.1004x over previous
#include <cuda_runtime.h>
#include <cuda_fp16.h>
#include <cstdint>

#define HNUM 12
#define DHEAD 64
#define BATCH 4
#define LQ 512
#define LK 512
#define DMODEL 768

// ---------------- scratch (device globals; no runtime alloc) ----------------
__device__ __half g_Qh[BATCH*HNUM*LQ*DHEAD];
__device__ __half g_Kh[BATCH*HNUM*LK*DHEAD];
__device__ __half g_Vth[(size_t)BATCH*HNUM*DHEAD*LK];   // [bh][d][tok]
__device__ float  g_S[(size_t)BATCH*HNUM*LQ*LK];
__device__ __half g_Ph[(size_t)BATCH*HNUM*LQ*LK];
__device__ float  g_PW[BATCH*HNUM*LQ*4];
__device__ uint32_t g_arc8[BATCH*512*512/4];
__device__ float  g_lnk[3*DHEAD];
__device__ float  g_lnv[3*DHEAD];

__device__ __forceinline__ float tf32_rna(float x) {
    uint32_t r;
    asm("cvt.rna.tf32.f32 %0, %1;" : "=r"(r) : "f"(x));
    return __uint_as_float(r);
}

#define MMA_TF32(d, a, b)                                                     \
    asm volatile("mma.sync.aligned.m16n8k8.row.col.f32.tf32.tf32.f32 "         \
        "{%0,%1,%2,%3}, {%4,%5,%6,%7}, {%8,%9}, {%0,%1,%2,%3};"                \
        : "+f"((d)[0]), "+f"((d)[1]), "+f"((d)[2]), "+f"((d)[3])               \
        : "r"(__float_as_uint((a)[0])), "r"(__float_as_uint((a)[1])),          \
          "r"(__float_as_uint((a)[2])), "r"(__float_as_uint((a)[3])),          \
          "r"(__float_as_uint((b)[0])), "r"(__float_as_uint((b)[1])))

#define MMA_F16(d, a, b)                                                      \
    asm volatile("mma.sync.aligned.m16n8k16.row.col.f32.f16.f16.f32 "          \
        "{%0,%1,%2,%3}, {%4,%5,%6,%7}, {%8,%9}, {%0,%1,%2,%3};"                \
        : "+f"((d)[0]), "+f"((d)[1]), "+f"((d)[2]), "+f"((d)[3])               \
        : "r"((a)[0]), "r"((a)[1]), "r"((a)[2]), "r"((a)[3]),                  \
          "r"((b)[0]), "r"((b)[1]))

#define CP_ASYNC16(dst, src) \
    asm volatile("cp.async.cg.shared.global [%0], [%1], 16;" :: "r"(dst), "l"(src) : "memory")
#define CP_COMMIT() asm volatile("cp.async.commit_group;" ::: "memory")
#define CP_WAIT1()  asm volatile("cp.async.wait_group 1;" ::: "memory")
#define CP_WAIT0()  asm volatile("cp.async.wait_group 0;" ::: "memory")

// ---------------- K1: arc pack (blocks 0..1023) + LN prep (block 1024) ------
__global__ __launch_bounds__(256) void prep_kernel(
    const int* __restrict__ arc,
    const float* __restrict__ dpk, const float* __restrict__ dpv,
    const float* __restrict__ kg, const float* __restrict__ kb,
    const float* __restrict__ vg, const float* __restrict__ vb) {
    if (blockIdx.x < 1024) {
        int i = blockIdx.x * 256 + threadIdx.x;
        const int4 a = *(const int4*)&arc[i * 4];
        g_arc8[i] = (uint32_t)a.x | ((uint32_t)a.y << 8) |
                    ((uint32_t)a.z << 16) | ((uint32_t)a.w << 24);
        return;
    }
    int w = threadIdx.x >> 5;
    int lane = threadIdx.x & 31;
    if (w >= 6) return;
    const float* src = (w < 3) ? dpk + w * DHEAD : dpv + (w - 3) * DHEAD;
    const float* g   = (w < 3) ? kg : vg;
    const float* be  = (w < 3) ? kb : vb;
    float* dst       = (w < 3) ? g_lnk + w * DHEAD : g_lnv + (w - 3) * DHEAD;
    float e0 = src[lane], e1 = src[lane + 32];
    float s = e0 + e1;
    #pragma unroll
    for (int o = 16; o; o >>= 1) s += __shfl_xor_sync(0xffffffffu, s, o);
    float mu = s * (1.0f / 64.0f);
    float d0 = e0 - mu, d1 = e1 - mu;
    float v = d0 * d0 + d1 * d1;
    #pragma unroll
    for (int o = 16; o; o >>= 1) v += __shfl_xor_sync(0xffffffffu, v, o);
    float rs = rsqrtf(v * (1.0f / 64.0f) + 1e-5f);
    dst[lane]      = d0 * rs * g[lane]      + be[lane];
    dst[lane + 32] = d1 * rs * g[lane + 32] + be[lane + 32];
}

// ---------------- K2: tf32 mma.sync QKV GEMM, half outputs -------------------
#define A_STRIDE 36
#define B_STRIDE 132
#define STAGE_FLOATS (128 * A_STRIDE + 32 * B_STRIDE)
#define GEMM_SMEM_BYTES (2 * STAGE_FLOATS * 4)

__global__ __launch_bounds__(256, 2) void qkv_gemm_mma_kernel(
    const float* __restrict__ hidden, const float* __restrict__ ctx,
    const float* __restrict__ Wq, const float* __restrict__ bq,
    const float* __restrict__ Wk, const float* __restrict__ bk,
    const float* __restrict__ Wv, const float* __restrict__ bv) {
    extern __shared__ float smem[];

    int sel = blockIdx.z;
    const float* X    = (sel == 0) ? hidden : ctx;
    const float* W    = (sel == 0) ? Wq : (sel == 1 ? Wk : Wv);
    const float* bias = (sel == 0) ? bq : (sel == 1 ? bk : bv);

    int m0 = blockIdx.x * 128;
    int n0 = blockIdx.y * 128;
    int t = threadIdx.x;
    int w = t >> 5;
    int lane = t & 31;
    int gid = lane >> 2;
    int tid4 = lane & 3;
    int wm = w >> 2;
    int wn = w & 3;

    auto load_chunk = [&](int c, int s) {
        int k0 = c * 32;
        float* sA = smem + s * STAGE_FLOATS;
        float* sB = sA + 128 * A_STRIDE;
        #pragma unroll
        for (int it = 0; it < 4; it++) {
            int idx = it * 256 + t;
            int r = idx >> 3, c4 = (idx & 7) << 2;
            uint32_t dst = (uint32_t)__cvta_generic_to_shared(&sA[r * A_STRIDE + c4]);
            CP_ASYNC16(dst, &X[(size_t)(m0 + r) * DMODEL + k0 + c4]);
        }
        #pragma unroll
        for (int it = 0; it < 4; it++) {
            int idx = it * 256 + t;
            int kr = idx >> 5, c4 = (idx & 31) << 2;
            uint32_t dst = (uint32_t)__cvta_generic_to_shared(&sB[kr * B_STRIDE + c4]);
            CP_ASYNC16(dst, &W[(size_t)(k0 + kr) * DMODEL + n0 + c4]);
        }
        CP_COMMIT();
    };

    float acc[4][4][4];
    #pragma unroll
    for (int mt = 0; mt < 4; mt++)
        #pragma unroll
        for (int nt = 0; nt < 4; nt++)
            #pragma unroll
            for (int f = 0; f < 4; f++) acc[mt][nt][f] = 0.f;

    load_chunk(0, 0);
    load_chunk(1, 1);
    CP_WAIT1();
    __syncthreads();

    for (int c = 0; c < 24; c++) {
        int s = c & 1;
        const float* sA = smem + s * STAGE_FLOATS;
        const float* sB = sA + 128 * A_STRIDE;
        #pragma unroll
        for (int ks = 0; ks < 4; ks++) {
            int k = ks * 8 + tid4;
            float afr[4][4];
            #pragma unroll
            for (int mt = 0; mt < 4; mt++) {
                int r = wm * 64 + mt * 16 + gid;
                afr[mt][0] = tf32_rna(sA[r * A_STRIDE + k]);
                afr[mt][1] = tf32_rna(sA[(r + 8) * A_STRIDE + k]);
                afr[mt][2] = tf32_rna(sA[r * A_STRIDE + k + 4]);
                afr[mt][3] = tf32_rna(sA[(r + 8) * A_STRIDE + k + 4]);
            }
            #pragma unroll
            for (int nt = 0; nt < 4; nt++) {
                int n = wn * 32 + nt * 8 + gid;
                float bfr[2];
                bfr[0] = tf32_rna(sB[k * B_STRIDE + n]);
                bfr[1] = tf32_rna(sB[(k + 4) * B_STRIDE + n]);
                #pragma unroll
                for (int mt = 0; mt < 4; mt++)
                    MMA_TF32(acc[mt][nt], afr[mt], bfr);
            }
        }
        __syncthreads();
        if (c + 2 < 24) {
            load_chunk(c + 2, s);
            CP_WAIT1();
        } else {
            CP_WAIT0();
        }
        __syncthreads();
    }

    float bv2[4][2];
    #pragma unroll
    for (int nt = 0; nt < 4; nt++) {
        int col = n0 + wn * 32 + nt * 8 + tid4 * 2;
        bv2[nt][0] = bias[col];
        bv2[nt][1] = bias[col + 1];
    }
    #pragma unroll
    for (int mt = 0; mt < 4; mt++) {
        #pragma unroll
        for (int half2i = 0; half2i < 2; half2i++) {
            int row = m0 + wm * 64 + mt * 16 + gid + half2i * 8;
            int b = row >> 9, tok = row & 511;
            #pragma unroll
            for (int nt = 0; nt < 4; nt++) {
                int col = n0 + wn * 32 + nt * 8 + tid4 * 2;
                int head = col >> 6, dh = col & 63;
                float vx = acc[mt][nt][half2i * 2 + 0] + bv2[nt][0];
                float vy = acc[mt][nt][half2i * 2 + 1] + bv2[nt][1];
                if (sel == 2) {
                    size_t base = ((size_t)(b * HNUM + head) * 64 + dh) * 512 + tok;
                    g_Vth[base]       = __float2half_rn(vx);
                    g_Vth[base + 512] = __float2half_rn(vy);
                } else {
                    __half* Out = (sel == 0) ? g_Qh : g_Kh;
                    __half2 hv = __floats2half2_rn(vx, vy);
                    *(__half2*)&Out[((size_t)(b * HNUM + head) * 512 + tok) * 64 + dh] = hv;
                }
            }
        }
    }
}

// ---------------- KA: S = Q K^T (f16 mma, f32 S out) -------------------------
#define QKW 36                                   // words per row (72 halfs)
#define QK_SMEM_BYTES (2 * 128 * QKW * 4)        // 36864

__global__ __launch_bounds__(256, 2) void qk_kernel() {
    extern __shared__ uint32_t sm32[];
    uint32_t* sQ = sm32;
    uint32_t* sK = sm32 + 128 * QKW;

    int bh = blockIdx.z;
    int q0 = blockIdx.x * 128;
    int k0 = blockIdx.y * 128;
    int t = threadIdx.x;
    int w = t >> 5;
    int lane = t & 31;
    int gid = lane >> 2;
    int tid4 = lane & 3;
    int wm = w >> 2;
    int wn = w & 3;

    const __half* Qbase = g_Qh + ((size_t)bh * 512 + q0) * 64;
    const __half* Kbase = g_Kh + ((size_t)bh * 512 + k0) * 64;

    // async load: each row = 128B = 8 x 16B chunks; 128 rows each tile
    #pragma unroll
    for (int it = 0; it < 4; it++) {
        int idx = it * 256 + t;
        int r = idx >> 3, c = idx & 7;
        uint32_t dq = (uint32_t)__cvta_generic_to_shared(&sQ[r * QKW + c * 4]);
        CP_ASYNC16(dq, (const char*)(Qbase + (size_t)r * 64) + c * 16);
        uint32_t dk = (uint32_t)__cvta_generic_to_shared(&sK[r * QKW + c * 4]);
        CP_ASYNC16(dk, (const char*)(Kbase + (size_t)r * 64) + c * 16);
    }
    CP_COMMIT();
    CP_WAIT0();
    __syncthreads();

    float acc[4][4][4];
    #pragma unroll
    for (int mt = 0; mt < 4; mt++)
        #pragma unroll
        for (int nt = 0; nt < 4; nt++)
            #pragma unroll
            for (int f = 0; f < 4; f++) acc[mt][nt][f] = 0.f;

    #pragma unroll
    for (int ks = 0; ks < 4; ks++) {
        int o = ks * 8;
        uint32_t afr[4][4];
        #pragma unroll
        for (int mt = 0; mt < 4; mt++) {
            int r = wm * 64 + mt * 16 + gid;
            afr[mt][0] = sQ[r * QKW + tid4 + o];
            afr[mt][1] = sQ[(r + 8) * QKW + tid4 + o];
            afr[mt][2] = sQ[r * QKW + tid4 + 4 + o];
            afr[mt][3] = sQ[(r + 8) * QKW + tid4 + 4 + o];
        }
        #pragma unroll
        for (int nt = 0; nt < 4; nt++) {
            int n = wn * 32 + nt * 8 + gid;
            uint32_t bfr[2];
            bfr[0] = sK[n * QKW + tid4 + o];
            bfr[1] = sK[n * QKW + tid4 + 4 + o];
            #pragma unroll
            for (int mt = 0; mt < 4; mt++)
                MMA_F16(acc[mt][nt], afr[mt], bfr);
        }
    }

    #pragma unroll
    for (int mt = 0; mt < 4; mt++) {
        #pragma unroll
        for (int hf = 0; hf < 2; hf++) {
            int q = q0 + wm * 64 + mt * 16 + gid + hf * 8;
            float* Srow = g_S + ((size_t)bh * 512 + q) * 512;
            #pragma unroll
            for (int nt = 0; nt < 4; nt++) {
                int col = k0 + wn * 32 + nt * 8 + tid4 * 2;
                *(float2*)&Srow[col] =
                    make_float2(acc[mt][nt][hf * 2], acc[mt][nt][hf * 2 + 1]);
            }
        }
    }
}

// ---------------- KB: row softmax + arc masses -> half P ---------------------
__global__ __launch_bounds__(256) void softmax_kernel(const float* __restrict__ mask) {
    int bh = blockIdx.y;
    int b = bh / HNUM;
    int q = blockIdx.x * 8 + (threadIdx.x >> 5);
    int lane = threadIdx.x & 31;

    const __half* Qrow = g_Qh + ((size_t)bh * 512 + q) * 64;
    float q0v = __half2float(Qrow[lane]), q1v = __half2float(Qrow[lane + 32]);
    float s0 = q0v * g_lnk[lane]       + q1v * g_lnk[lane + 32];
    float s1 = q0v * g_lnk[64 + lane]  + q1v * g_lnk[96 + lane];
    float s2 = q0v * g_lnk[128 + lane] + q1v * g_lnk[160 + lane];
    #pragma unroll
    for (int o = 16; o; o >>= 1) {
        s0 += __shfl_xor_sync(0xffffffffu, s0, o);
        s1 += __shfl_xor_sync(0xffffffffu, s1, o);
        s2 += __shfl_xor_sync(0xffffffffu, s2, o);
    }

    const float* Srow = g_S + ((size_t)bh * 512 + q) * 512;
    const uint32_t* arcw = g_arc8 + ((size_t)(b * 512 + q)) * 128 + lane * 4;
    const float* mrow = mask + b * 512 + lane * 16;

    float x[16];
    int a[16];
    #pragma unroll
    for (int j = 0; j < 4; j++) {
        float4 sv = *(const float4*)&Srow[lane * 16 + j * 4];
        float4 mv = *(const float4*)&mrow[j * 4];
        uint32_t aw = arcw[j];
        a[j*4+0] = aw & 3;          a[j*4+1] = (aw >> 8) & 3;
        a[j*4+2] = (aw >> 16) & 3;  a[j*4+3] = (aw >> 24) & 3;
        float q0s = (a[j*4+0] == 0) ? s0 : ((a[j*4+0] == 1) ? s1 : s2);
        float q1s = (a[j*4+1] == 0) ? s0 : ((a[j*4+1] == 1) ? s1 : s2);
        float q2s = (a[j*4+2] == 0) ? s0 : ((a[j*4+2] == 1) ? s1 : s2);
        float q3s = (a[j*4+3] == 0) ? s0 : ((a[j*4+3] == 1) ? s1 : s2);
        x[j*4+0] = sv.x * 0.125f + q0s + mv.x;
        x[j*4+1] = sv.y * 0.125f + q1s + mv.y;
        x[j*4+2] = sv.z * 0.125f + q2s + mv.z;
        x[j*4+3] = sv.w * 0.125f + q3s + mv.w;
    }
    float mx = x[0];
    #pragma unroll
    for (int j = 1; j < 16; j++) mx = fmaxf(mx, x[j]);
    #pragma unroll
    for (int o = 16; o; o >>= 1) mx = fmaxf(mx, __shfl_xor_sync(0xffffffffu, mx, o));

    float sum = 0.f, p1 = 0.f, p2 = 0.f;
    #pragma unroll
    for (int j = 0; j < 16; j++) {
        float p = __expf(x[j] - mx);
        x[j] = p;
        sum += p;
        p1 += (a[j] == 1) ? p : 0.f;
        p2 += (a[j] == 2) ? p : 0.f;
    }
    #pragma unroll
    for (int o = 16; o; o >>= 1) {
        sum += __shfl_xor_sync(0xffffffffu, sum, o);
        p1  += __shfl_xor_sync(0xffffffffu, p1, o);
        p2  += __shfl_xor_sync(0xffffffffu, p2, o);
    }
    float inv = 1.f / sum;

    __half* Prow = g_Ph + ((size_t)bh * 512 + q) * 512;
    #pragma unroll
    for (int j = 0; j < 4; j++) {
        __half2 h0 = __floats2half2_rn(x[j*4+0] * inv, x[j*4+1] * inv);
        __half2 h1 = __floats2half2_rn(x[j*4+2] * inv, x[j*4+3] * inv);
        *(__half2*)&Prow[lane * 16 + j * 4]     = h0;
        *(__half2*)&Prow[lane * 16 + j * 4 + 2] = h1;
    }
    if (lane == 0) {
        float p0 = sum - p1 - p2;
        float4 pwv = make_float4(p0 * inv, p1 * inv, p2 * inv, 0.f);
        *(float4*)&g_PW[((size_t)bh * 512 + q) * 4] = pwv;
    }
}

// ---------------- KC: O = P V + pw . lnv  (f16 mma) --------------------------
#define PVW 20                                       // words/row (40 halfs)
#define PV_STAGE_W (64 * PVW + 64 * PVW)             // P tile + Vt tile words
#define PV_SMEM_BYTES (2 * PV_STAGE_W * 4)           // 20480

__global__ __launch_bounds__(256, 4) void pv_kernel(float* __restrict__ out) {
    extern __shared__ uint32_t sm32[];

    int bh = blockIdx.y;
    int b = bh / HNUM, h = bh % HNUM;
    int q0 = blockIdx.x * 64;
    int t = threadIdx.x;
    int w = t >> 5;
    int lane = t & 31;
    int gid = lane >> 2;
    int tid4 = lane & 3;
    int wm = w >> 1;
    int wn = w & 1;

    const __half* Pbase = g_Ph + ((size_t)bh * 512 + q0) * 512;
    const __half* Vtbase = g_Vth + (size_t)bh * 64 * 512;

    auto load_chunk = [&](int c, int s) {
        int k0 = c * 32;
        uint32_t* sP = sm32 + s * PV_STAGE_W;
        uint32_t* sV = sP + 64 * PVW;
        // P: 64 rows x 32 halfs (64B = 4 x 16B); Vt: 64 rows x 32 halfs
        {
            int r = t >> 2, c4 = t & 3;           // 256 threads = 64 rows x 4
            uint32_t dp = (uint32_t)__cvta_generic_to_shared(&sP[r * PVW + c4 * 4]);
            CP_ASYNC16(dp, (const char*)(Pbase + (size_t)r * 512 + k0) + c4 * 16);
            uint32_t dv = (uint32_t)__cvta_generic_to_shared(&sV[r * PVW + c4 * 4]);
            CP_ASYNC16(dv, (const char*)(Vtbase + (size_t)r * 512 + k0) + c4 * 16);
        }
        CP_COMMIT();
    };

    float acc[4][4];
    #pragma unroll
    for (int nt = 0; nt < 4; nt++)
        #pragma unroll
        for (int f = 0; f < 4; f++) acc[nt][f] = 0.f;

    load_chunk(0, 0);
    load_chunk(1, 1);
    CP_WAIT1();
    __syncthreads();

    for (int c = 0; c < 16; c++) {
        int s = c & 1;
        const uint32_t* sP = sm32 + s * PV_STAGE_W;
        const uint32_t* sV = sP + 64 * PVW;
        #pragma unroll
        for (int ks = 0; ks < 2; ks++) {
            int o = ks * 8;
            uint32_t afr[4];
            int r = wm * 16 + gid;
            afr[0] = sP[r * PVW + tid4 + o];
            afr[1] = sP[(r + 8) * PVW + tid4 + o];
            afr[2] = sP[r * PVW + tid4 + 4 + o];
            afr[3] = sP[(r + 8) * PVW + tid4 + 4 + o];
            #pragma unroll
            for (int nt = 0; nt < 4; nt++) {
                int n = wn * 32 + nt * 8 + gid;
                uint32_t bfr[2];
                bfr[0] = sV[n * PVW + tid4 + o];
                bfr[1] = sV[n * PVW + tid4 + 4 + o];
                MMA_F16(acc[nt], afr, bfr);
            }
        }
        __syncthreads();
        if (c + 2 < 16) {
            load_chunk(c + 2, s);
            CP_WAIT1();
        } else {
            CP_WAIT0();
        }
        __syncthreads();
    }

    int r0 = wm * 16 + gid, r1 = r0 + 8;
    float4 pw0 = *(float4*)&g_PW[((size_t)bh * 512 + q0 + r0) * 4];
    float4 pw1 = *(float4*)&g_PW[((size_t)bh * 512 + q0 + r1) * 4];
    #pragma unroll
    for (int nt = 0; nt < 4; nt++) {
        int col = wn * 32 + nt * 8 + tid4 * 2;
        float l0a = g_lnv[col],       l0b = g_lnv[col + 1];
        float l1a = g_lnv[64 + col],  l1b = g_lnv[64 + col + 1];
        float l2a = g_lnv[128 + col], l2b = g_lnv[128 + col + 1];
        float2 v0, v1;
        v0.x = acc[nt][0] + pw0.x * l0a + pw0.y * l1a + pw0.z * l2a;
        v0.y = acc[nt][1] + pw0.x * l0b + pw0.y * l1b + pw0.z * l2b;
        v1.x = acc[nt][2] + pw1.x * l0a + pw1.y * l1a + pw1.z * l2a;
        v1.y = acc[nt][3] + pw1.x * l0b + pw1.y * l1b + pw1.z * l2b;
        *(float2*)&out[(size_t)(b * 512 + q0 + r0) * 768 + h * 64 + col] = v0;
        *(float2*)&out[(size_t)(b * 512 + q0 + r1) * 768 + h * 64 + col] = v1;
    }
}

// ---------------- launcher ----------------------------------------------------
extern "C" void kernel_launch(void* const* d_in, const int* in_sizes, int n_in,
                              void* d_out, int out_size) {
    const float* hidden = (const float*)d_in[0];
    const float* ctx    = (const float*)d_in[1];
    const float* mask   = (const float*)d_in[2];
    const int*   arc    = (const int*)d_in[3];
    const float* Wq = (const float*)d_in[4];  const float* bq = (const float*)d_in[5];
    const float* Wk = (const float*)d_in[6];  const float* bk = (const float*)d_in[7];
    const float* Wv = (const float*)d_in[8];  const float* bv = (const float*)d_in[9];
    const float* dpk = (const float*)d_in[10]; const float* dpv = (const float*)d_in[11];
    const float* lkg = (const float*)d_in[12]; const float* lkb = (const float*)d_in[13];
    const float* lvg = (const float*)d_in[14]; const float* lvb = (const float*)d_in[15];
    float* out = (float*)d_out;

    prep_kernel<<<1025, 256>>>(arc, dpk, dpv, lkg, lkb, lvg, lvb);

    cudaFuncSetAttribute(qkv_gemm_mma_kernel, cudaFuncAttributeMaxDynamicSharedMemorySize,
                         GEMM_SMEM_BYTES);
    qkv_gemm_mma_kernel<<<dim3(16, 6, 3), 256, GEMM_SMEM_BYTES>>>(
        hidden, ctx, Wq, bq, Wk, bk, Wv, bv);

    cudaFuncSetAttribute(qk_kernel, cudaFuncAttributeMaxDynamicSharedMemorySize,
                         QK_SMEM_BYTES);
    qk_kernel<<<dim3(4, 4, 48), 256, QK_SMEM_BYTES>>>();

    softmax_kernel<<<dim3(64, 48), 256>>>(mask);

    cudaFuncSetAttribute(pv_kernel, cudaFuncAttributeMaxDynamicSharedMemorySize,
                         PV_SMEM_BYTES);
    pv_kernel<<<dim3(8, 48), 256, PV_SMEM_BYTES>>>(out);
}

// round 10
// speedup vs baseline: 1.6352x; 1.3192x over previous
#include <cuda_runtime.h>
#include <cuda_fp16.h>
#include <cstdint>

#define HNUM 12
#define DHEAD 64
#define BATCH 4
#define LQ 512
#define LK 512
#define DMODEL 768
#define XSIZE (BATCH*LQ*DMODEL)

// ---------------- scratch (device globals; no runtime alloc) ----------------
__device__ __half g_Xh[2*XSIZE];                        // hidden | ctx as half
__device__ __half g_Wth[3][DMODEL*DMODEL];              // W transposed [n][k]
__device__ __half g_Qh[BATCH*HNUM*LQ*DHEAD];
__device__ __half g_Kh[BATCH*HNUM*LK*DHEAD];
__device__ __half g_Vth[(size_t)BATCH*HNUM*DHEAD*LK];   // [bh][d][tok]
__device__ float  g_S[(size_t)BATCH*HNUM*LQ*LK];
__device__ __half g_Ph[(size_t)BATCH*HNUM*LQ*LK];
__device__ float  g_PW[BATCH*HNUM*LQ*4];
__device__ uint32_t g_arc8[BATCH*512*512/4];
__device__ float  g_lnk[3*DHEAD];
__device__ float  g_lnv[3*DHEAD];

#define MMA_F16(d, a, b)                                                      \
    asm volatile("mma.sync.aligned.m16n8k16.row.col.f32.f16.f16.f32 "          \
        "{%0,%1,%2,%3}, {%4,%5,%6,%7}, {%8,%9}, {%0,%1,%2,%3};"                \
        : "+f"((d)[0]), "+f"((d)[1]), "+f"((d)[2]), "+f"((d)[3])               \
        : "r"((a)[0]), "r"((a)[1]), "r"((a)[2]), "r"((a)[3]),                  \
          "r"((b)[0]), "r"((b)[1]))

#define CP_ASYNC16(dst, src) \
    asm volatile("cp.async.cg.shared.global [%0], [%1], 16;" :: "r"(dst), "l"(src) : "memory")
#define CP_COMMIT() asm volatile("cp.async.commit_group;" ::: "memory")
#define CP_WAIT1()  asm volatile("cp.async.wait_group 1;" ::: "memory")
#define CP_WAIT0()  asm volatile("cp.async.wait_group 0;" ::: "memory")

// ---------------- K1: arc pack | X convert | W transpose-convert | LN -------
// blocks: [0,1024) arc, [1024,2560) hidden, [2560,4096) ctx,
//         [4096,5824) W transpose, 5824 LN
__global__ __launch_bounds__(256) void prep_kernel(
    const int* __restrict__ arc,
    const float* __restrict__ hidden, const float* __restrict__ ctx,
    const float* __restrict__ Wq, const float* __restrict__ Wk,
    const float* __restrict__ Wv,
    const float* __restrict__ dpk, const float* __restrict__ dpv,
    const float* __restrict__ kg, const float* __restrict__ kb,
    const float* __restrict__ vg, const float* __restrict__ vb) {
    int bx = blockIdx.x;
    int t = threadIdx.x;
    if (bx < 1024) {
        int i = bx * 256 + t;
        const int4 a = *(const int4*)&arc[i * 4];
        g_arc8[i] = (uint32_t)a.x | ((uint32_t)a.y << 8) |
                    ((uint32_t)a.z << 16) | ((uint32_t)a.w << 24);
        return;
    }
    if (bx < 4096) {
        bool is_h = bx < 2560;
        const float* src = is_h ? hidden : ctx;
        __half* dst = g_Xh + (is_h ? 0 : XSIZE);
        int i = ((bx - (is_h ? 1024 : 2560)) * 256 + t) * 4;
        float4 v = *(const float4*)&src[i];
        __half2 h0 = __floats2half2_rn(v.x, v.y);
        __half2 h1 = __floats2half2_rn(v.z, v.w);
        *(__half2*)&dst[i] = h0;
        *(__half2*)&dst[i + 2] = h1;
        return;
    }
    if (bx < 5824) {
        __shared__ float tile[32][33];
        int wb = bx - 4096;
        int sel = wb / 576;
        int tl = wb % 576;
        int tx0 = (tl % 24) * 32, ty0 = (tl / 24) * 32;
        const float* W = (sel == 0) ? Wq : (sel == 1 ? Wk : Wv);
        __half* WT = g_Wth[sel];
        int tx = t & 31, ty = t >> 5;
        #pragma unroll
        for (int i = 0; i < 32; i += 8)
            tile[ty + i][tx] = W[(size_t)(ty0 + ty + i) * DMODEL + tx0 + tx];
        __syncthreads();
        #pragma unroll
        for (int i = 0; i < 32; i += 8)
            WT[(size_t)(tx0 + ty + i) * DMODEL + ty0 + tx] =
                __float2half_rn(tile[tx][ty + i]);
        return;
    }
    // LN prep
    int w = t >> 5;
    int lane = t & 31;
    if (w >= 6) return;
    const float* src = (w < 3) ? dpk + w * DHEAD : dpv + (w - 3) * DHEAD;
    const float* g   = (w < 3) ? kg : vg;
    const float* be  = (w < 3) ? kb : vb;
    float* dst       = (w < 3) ? g_lnk + w * DHEAD : g_lnv + (w - 3) * DHEAD;
    float e0 = src[lane], e1 = src[lane + 32];
    float s = e0 + e1;
    #pragma unroll
    for (int o = 16; o; o >>= 1) s += __shfl_xor_sync(0xffffffffu, s, o);
    float mu = s * (1.0f / 64.0f);
    float d0 = e0 - mu, d1 = e1 - mu;
    float v = d0 * d0 + d1 * d1;
    #pragma unroll
    for (int o = 16; o; o >>= 1) v += __shfl_xor_sync(0xffffffffu, v, o);
    float rs = rsqrtf(v * (1.0f / 64.0f) + 1e-5f);
    dst[lane]      = d0 * rs * g[lane]      + be[lane];
    dst[lane + 32] = d1 * rs * g[lane + 32] + be[lane + 32];
}

// ---------------- K2: f16 mma.sync QKV GEMM ----------------------------------
// K-chunks of 64 halfs; row stride 36 words (72 halfs) -> conflict-free frags.
#define GW 36
#define G_STAGE_W (128 * GW * 2)                    // A tile + B tile words
#define GEMM_SMEM_BYTES (2 * G_STAGE_W * 4)         // 73728

__global__ __launch_bounds__(256, 2) void qkv_gemm_f16_kernel(
    const float* __restrict__ bq, const float* __restrict__ bk,
    const float* __restrict__ bv) {
    extern __shared__ uint32_t sm32[];

    int sel = blockIdx.z;
    const __half* Xh = g_Xh + ((sel == 0) ? 0 : XSIZE);
    const __half* Wth = g_Wth[sel];
    const float* bias = (sel == 0) ? bq : (sel == 1 ? bk : bv);

    int m0 = blockIdx.x * 128;
    int n0 = blockIdx.y * 128;
    int t = threadIdx.x;
    int w = t >> 5;
    int lane = t & 31;
    int gid = lane >> 2;
    int tid4 = lane & 3;
    int wm = w >> 2;
    int wn = w & 3;

    auto load_chunk = [&](int c, int s) {
        int k0 = c * 64;
        uint32_t* sA = sm32 + s * G_STAGE_W;
        uint32_t* sB = sA + 128 * GW;
        #pragma unroll
        for (int it = 0; it < 4; it++) {
            int idx = it * 256 + t;
            int r = idx >> 3, c8 = idx & 7;
            uint32_t da = (uint32_t)__cvta_generic_to_shared(&sA[r * GW + c8 * 4]);
            CP_ASYNC16(da, (const char*)(Xh + (size_t)(m0 + r) * DMODEL + k0) + c8 * 16);
            uint32_t db = (uint32_t)__cvta_generic_to_shared(&sB[r * GW + c8 * 4]);
            CP_ASYNC16(db, (const char*)(Wth + (size_t)(n0 + r) * DMODEL + k0) + c8 * 16);
        }
        CP_COMMIT();
    };

    float acc[4][4][4];
    #pragma unroll
    for (int mt = 0; mt < 4; mt++)
        #pragma unroll
        for (int nt = 0; nt < 4; nt++)
            #pragma unroll
            for (int f = 0; f < 4; f++) acc[mt][nt][f] = 0.f;

    load_chunk(0, 0);
    load_chunk(1, 1);
    CP_WAIT1();
    __syncthreads();

    for (int c = 0; c < 12; c++) {
        int s = c & 1;
        const uint32_t* sA = sm32 + s * G_STAGE_W;
        const uint32_t* sB = sA + 128 * GW;
        #pragma unroll
        for (int ks = 0; ks < 4; ks++) {
            int o = ks * 8;
            uint32_t afr[4][4];
            #pragma unroll
            for (int mt = 0; mt < 4; mt++) {
                int r = wm * 64 + mt * 16 + gid;
                afr[mt][0] = sA[r * GW + tid4 + o];
                afr[mt][1] = sA[(r + 8) * GW + tid4 + o];
                afr[mt][2] = sA[r * GW + tid4 + 4 + o];
                afr[mt][3] = sA[(r + 8) * GW + tid4 + 4 + o];
            }
            #pragma unroll
            for (int nt = 0; nt < 4; nt++) {
                int n = wn * 32 + nt * 8 + gid;
                uint32_t bfr[2];
                bfr[0] = sB[n * GW + tid4 + o];
                bfr[1] = sB[n * GW + tid4 + 4 + o];
                #pragma unroll
                for (int mt = 0; mt < 4; mt++)
                    MMA_F16(acc[mt][nt], afr[mt], bfr);
            }
        }
        __syncthreads();
        if (c + 2 < 12) {
            load_chunk(c + 2, s);
            CP_WAIT1();
        } else {
            CP_WAIT0();
        }
        __syncthreads();
    }

    float bv2[4][2];
    #pragma unroll
    for (int nt = 0; nt < 4; nt++) {
        int col = n0 + wn * 32 + nt * 8 + tid4 * 2;
        bv2[nt][0] = bias[col];
        bv2[nt][1] = bias[col + 1];
    }
    #pragma unroll
    for (int mt = 0; mt < 4; mt++) {
        #pragma unroll
        for (int hf = 0; hf < 2; hf++) {
            int row = m0 + wm * 64 + mt * 16 + gid + hf * 8;
            int b = row >> 9, tok = row & 511;
            #pragma unroll
            for (int nt = 0; nt < 4; nt++) {
                int col = n0 + wn * 32 + nt * 8 + tid4 * 2;
                int head = col >> 6, dh = col & 63;
                float vx = acc[mt][nt][hf * 2 + 0] + bv2[nt][0];
                float vy = acc[mt][nt][hf * 2 + 1] + bv2[nt][1];
                if (sel == 2) {
                    size_t base = ((size_t)(b * HNUM + head) * 64 + dh) * 512 + tok;
                    g_Vth[base]       = __float2half_rn(vx);
                    g_Vth[base + 512] = __float2half_rn(vy);
                } else {
                    __half* Out = (sel == 0) ? g_Qh : g_Kh;
                    __half2 hv = __floats2half2_rn(vx, vy);
                    *(__half2*)&Out[((size_t)(b * HNUM + head) * 512 + tok) * 64 + dh] = hv;
                }
            }
        }
    }
}

// ---------------- KA: S = QK^T * 0.125 + mask (f16 mma) ----------------------
#define QKW 36
#define QK_SMEM_BYTES ((2 * 128 * QKW + 128) * 4)

__global__ __launch_bounds__(256, 2) void qk_kernel(const float* __restrict__ mask) {
    extern __shared__ uint32_t sm32[];
    uint32_t* sQ = sm32;
    uint32_t* sK = sm32 + 128 * QKW;
    float* sMask = (float*)(sm32 + 2 * 128 * QKW);

    int bh = blockIdx.z;
    int b = bh / HNUM;
    int q0 = blockIdx.x * 128;
    int k0 = blockIdx.y * 128;
    int t = threadIdx.x;
    int w = t >> 5;
    int lane = t & 31;
    int gid = lane >> 2;
    int tid4 = lane & 3;
    int wm = w >> 2;
    int wn = w & 3;

    const __half* Qbase = g_Qh + ((size_t)bh * 512 + q0) * 64;
    const __half* Kbase = g_Kh + ((size_t)bh * 512 + k0) * 64;

    #pragma unroll
    for (int it = 0; it < 4; it++) {
        int idx = it * 256 + t;
        int r = idx >> 3, c = idx & 7;
        uint32_t dq = (uint32_t)__cvta_generic_to_shared(&sQ[r * QKW + c * 4]);
        CP_ASYNC16(dq, (const char*)(Qbase + (size_t)r * 64) + c * 16);
        uint32_t dk = (uint32_t)__cvta_generic_to_shared(&sK[r * QKW + c * 4]);
        CP_ASYNC16(dk, (const char*)(Kbase + (size_t)r * 64) + c * 16);
    }
    CP_COMMIT();
    if (t < 128) sMask[t] = mask[b * 512 + k0 + t];
    CP_WAIT0();
    __syncthreads();

    float acc[4][4][4];
    #pragma unroll
    for (int mt = 0; mt < 4; mt++)
        #pragma unroll
        for (int nt = 0; nt < 4; nt++)
            #pragma unroll
            for (int f = 0; f < 4; f++) acc[mt][nt][f] = 0.f;

    #pragma unroll
    for (int ks = 0; ks < 4; ks++) {
        int o = ks * 8;
        uint32_t afr[4][4];
        #pragma unroll
        for (int mt = 0; mt < 4; mt++) {
            int r = wm * 64 + mt * 16 + gid;
            afr[mt][0] = sQ[r * QKW + tid4 + o];
            afr[mt][1] = sQ[(r + 8) * QKW + tid4 + o];
            afr[mt][2] = sQ[r * QKW + tid4 + 4 + o];
            afr[mt][3] = sQ[(r + 8) * QKW + tid4 + 4 + o];
        }
        #pragma unroll
        for (int nt = 0; nt < 4; nt++) {
            int n = wn * 32 + nt * 8 + gid;
            uint32_t bfr[2];
            bfr[0] = sK[n * QKW + tid4 + o];
            bfr[1] = sK[n * QKW + tid4 + 4 + o];
            #pragma unroll
            for (int mt = 0; mt < 4; mt++)
                MMA_F16(acc[mt][nt], afr[mt], bfr);
        }
    }

    #pragma unroll
    for (int mt = 0; mt < 4; mt++) {
        #pragma unroll
        for (int hf = 0; hf < 2; hf++) {
            int q = q0 + wm * 64 + mt * 16 + gid + hf * 8;
            float* Srow = g_S + ((size_t)bh * 512 + q) * 512;
            #pragma unroll
            for (int nt = 0; nt < 4; nt++) {
                int lc = wn * 32 + nt * 8 + tid4 * 2;
                float2 sv;
                sv.x = acc[mt][nt][hf * 2 + 0] * 0.125f + sMask[lc];
                sv.y = acc[mt][nt][hf * 2 + 1] * 0.125f + sMask[lc + 1];
                *(float2*)&Srow[k0 + lc] = sv;
            }
        }
    }
}

// ---------------- KB: row softmax (no-max) + arc masses -> half P ------------
__global__ __launch_bounds__(256) void softmax_kernel() {
    int bh = blockIdx.y;
    int b = bh / HNUM;
    int q = blockIdx.x * 8 + (threadIdx.x >> 5);
    int lane = threadIdx.x & 31;

    const __half* Qrow = g_Qh + ((size_t)bh * 512 + q) * 64;
    float q0v = __half2float(Qrow[lane]), q1v = __half2float(Qrow[lane + 32]);
    float s0 = q0v * g_lnk[lane]       + q1v * g_lnk[lane + 32];
    float s1 = q0v * g_lnk[64 + lane]  + q1v * g_lnk[96 + lane];
    float s2 = q0v * g_lnk[128 + lane] + q1v * g_lnk[160 + lane];
    #pragma unroll
    for (int o = 16; o; o >>= 1) {
        s0 += __shfl_xor_sync(0xffffffffu, s0, o);
        s1 += __shfl_xor_sync(0xffffffffu, s1, o);
        s2 += __shfl_xor_sync(0xffffffffu, s2, o);
    }

    const float* Srow = g_S + ((size_t)bh * 512 + q) * 512;
    const uint32_t* arcw = g_arc8 + ((size_t)(b * 512 + q)) * 128 + lane * 4;

    float x[16];
    float sum = 0.f, p1 = 0.f, p2 = 0.f;
    #pragma unroll
    for (int j = 0; j < 4; j++) {
        float4 sv = *(const float4*)&Srow[lane * 16 + j * 4];
        uint32_t aw = arcw[j];
        int a0 = aw & 3, a1 = (aw >> 8) & 3, a2 = (aw >> 16) & 3, a3 = (aw >> 24) & 3;
        float e0 = __expf(sv.x + ((a0 == 0) ? s0 : ((a0 == 1) ? s1 : s2)));
        float e1 = __expf(sv.y + ((a1 == 0) ? s0 : ((a1 == 1) ? s1 : s2)));
        float e2 = __expf(sv.z + ((a2 == 0) ? s0 : ((a2 == 1) ? s1 : s2)));
        float e3 = __expf(sv.w + ((a3 == 0) ? s0 : ((a3 == 1) ? s1 : s2)));
        x[j*4+0] = e0; x[j*4+1] = e1; x[j*4+2] = e2; x[j*4+3] = e3;
        sum += e0 + e1 + e2 + e3;
        p1 += ((a0 == 1) ? e0 : 0.f) + ((a1 == 1) ? e1 : 0.f)
            + ((a2 == 1) ? e2 : 0.f) + ((a3 == 1) ? e3 : 0.f);
        p2 += ((a0 == 2) ? e0 : 0.f) + ((a1 == 2) ? e1 : 0.f)
            + ((a2 == 2) ? e2 : 0.f) + ((a3 == 2) ? e3 : 0.f);
    }
    #pragma unroll
    for (int o = 16; o; o >>= 1) {
        sum += __shfl_xor_sync(0xffffffffu, sum, o);
        p1  += __shfl_xor_sync(0xffffffffu, p1, o);
        p2  += __shfl_xor_sync(0xffffffffu, p2, o);
    }
    float inv = 1.f / sum;

    __half* Prow = g_Ph + ((size_t)bh * 512 + q) * 512;
    #pragma unroll
    for (int j = 0; j < 4; j++) {
        __half2 h0 = __floats2half2_rn(x[j*4+0] * inv, x[j*4+1] * inv);
        __half2 h1 = __floats2half2_rn(x[j*4+2] * inv, x[j*4+3] * inv);
        *(__half2*)&Prow[lane * 16 + j * 4]     = h0;
        *(__half2*)&Prow[lane * 16 + j * 4 + 2] = h1;
    }
    if (lane == 0) {
        float p0 = sum - p1 - p2;
        float4 pwv = make_float4(p0 * inv, p1 * inv, p2 * inv, 0.f);
        *(float4*)&g_PW[((size_t)bh * 512 + q) * 4] = pwv;
    }
}

// ---------------- KC: O = P V + pw . lnv  (f16 mma) --------------------------
#define PVW 20
#define PV_STAGE_W (64 * PVW + 64 * PVW)
#define PV_SMEM_BYTES (2 * PV_STAGE_W * 4)

__global__ __launch_bounds__(256, 4) void pv_kernel(float* __restrict__ out) {
    extern __shared__ uint32_t sm32[];

    int bh = blockIdx.y;
    int b = bh / HNUM, h = bh % HNUM;
    int q0 = blockIdx.x * 64;
    int t = threadIdx.x;
    int w = t >> 5;
    int lane = t & 31;
    int gid = lane >> 2;
    int tid4 = lane & 3;
    int wm = w >> 1;
    int wn = w & 1;

    const __half* Pbase = g_Ph + ((size_t)bh * 512 + q0) * 512;
    const __half* Vtbase = g_Vth + (size_t)bh * 64 * 512;

    auto load_chunk = [&](int c, int s) {
        int k0 = c * 32;
        uint32_t* sP = sm32 + s * PV_STAGE_W;
        uint32_t* sV = sP + 64 * PVW;
        int r = t >> 2, c4 = t & 3;
        uint32_t dp = (uint32_t)__cvta_generic_to_shared(&sP[r * PVW + c4 * 4]);
        CP_ASYNC16(dp, (const char*)(Pbase + (size_t)r * 512 + k0) + c4 * 16);
        uint32_t dv = (uint32_t)__cvta_generic_to_shared(&sV[r * PVW + c4 * 4]);
        CP_ASYNC16(dv, (const char*)(Vtbase + (size_t)r * 512 + k0) + c4 * 16);
        CP_COMMIT();
    };

    float acc[4][4];
    #pragma unroll
    for (int nt = 0; nt < 4; nt++)
        #pragma unroll
        for (int f = 0; f < 4; f++) acc[nt][f] = 0.f;

    load_chunk(0, 0);
    load_chunk(1, 1);
    CP_WAIT1();
    __syncthreads();

    for (int c = 0; c < 16; c++) {
        int s = c & 1;
        const uint32_t* sP = sm32 + s * PV_STAGE_W;
        const uint32_t* sV = sP + 64 * PVW;
        #pragma unroll
        for (int ks = 0; ks < 2; ks++) {
            int o = ks * 8;
            uint32_t afr[4];
            int r = wm * 16 + gid;
            afr[0] = sP[r * PVW + tid4 + o];
            afr[1] = sP[(r + 8) * PVW + tid4 + o];
            afr[2] = sP[r * PVW + tid4 + 4 + o];
            afr[3] = sP[(r + 8) * PVW + tid4 + 4 + o];
            #pragma unroll
            for (int nt = 0; nt < 4; nt++) {
                int n = wn * 32 + nt * 8 + gid;
                uint32_t bfr[2];
                bfr[0] = sV[n * PVW + tid4 + o];
                bfr[1] = sV[n * PVW + tid4 + 4 + o];
                MMA_F16(acc[nt], afr, bfr);
            }
        }
        __syncthreads();
        if (c + 2 < 16) {
            load_chunk(c + 2, s);
            CP_WAIT1();
        } else {
            CP_WAIT0();
        }
        __syncthreads();
    }

    int r0 = wm * 16 + gid, r1 = r0 + 8;
    float4 pw0 = *(float4*)&g_PW[((size_t)bh * 512 + q0 + r0) * 4];
    float4 pw1 = *(float4*)&g_PW[((size_t)bh * 512 + q0 + r1) * 4];
    #pragma unroll
    for (int nt = 0; nt < 4; nt++) {
        int col = wn * 32 + nt * 8 + tid4 * 2;
        float l0a = g_lnv[col],       l0b = g_lnv[col + 1];
        float l1a = g_lnv[64 + col],  l1b = g_lnv[64 + col + 1];
        float l2a = g_lnv[128 + col], l2b = g_lnv[128 + col + 1];
        float2 v0, v1;
        v0.x = acc[nt][0] + pw0.x * l0a + pw0.y * l1a + pw0.z * l2a;
        v0.y = acc[nt][1] + pw0.x * l0b + pw0.y * l1b + pw0.z * l2b;
        v1.x = acc[nt][2] + pw1.x * l0a + pw1.y * l1a + pw1.z * l2a;
        v1.y = acc[nt][3] + pw1.x * l0b + pw1.y * l1b + pw1.z * l2b;
        *(float2*)&out[(size_t)(b * 512 + q0 + r0) * 768 + h * 64 + col] = v0;
        *(float2*)&out[(size_t)(b * 512 + q0 + r1) * 768 + h * 64 + col] = v1;
    }
}

// ---------------- launcher ----------------------------------------------------
extern "C" void kernel_launch(void* const* d_in, const int* in_sizes, int n_in,
                              void* d_out, int out_size) {
    const float* hidden = (const float*)d_in[0];
    const float* ctx    = (const float*)d_in[1];
    const float* mask   = (const float*)d_in[2];
    const int*   arc    = (const int*)d_in[3];
    const float* Wq = (const float*)d_in[4];  const float* bq = (const float*)d_in[5];
    const float* Wk = (const float*)d_in[6];  const float* bk = (const float*)d_in[7];
    const float* Wv = (const float*)d_in[8];  const float* bv = (const float*)d_in[9];
    const float* dpk = (const float*)d_in[10]; const float* dpv = (const float*)d_in[11];
    const float* lkg = (const float*)d_in[12]; const float* lkb = (const float*)d_in[13];
    const float* lvg = (const float*)d_in[14]; const float* lvb = (const float*)d_in[15];
    float* out = (float*)d_out;

    prep_kernel<<<5825, 256>>>(arc, hidden, ctx, Wq, Wk, Wv,
                               dpk, dpv, lkg, lkb, lvg, lvb);

    cudaFuncSetAttribute(qkv_gemm_f16_kernel, cudaFuncAttributeMaxDynamicSharedMemorySize,
                         GEMM_SMEM_BYTES);
    qkv_gemm_f16_kernel<<<dim3(16, 6, 3), 256, GEMM_SMEM_BYTES>>>(bq, bk, bv);

    cudaFuncSetAttribute(qk_kernel, cudaFuncAttributeMaxDynamicSharedMemorySize,
                         QK_SMEM_BYTES);
    qk_kernel<<<dim3(4, 4, 48), 256, QK_SMEM_BYTES>>>(mask);

    softmax_kernel<<<dim3(64, 48), 256>>>();

    cudaFuncSetAttribute(pv_kernel, cudaFuncAttributeMaxDynamicSharedMemorySize,
                         PV_SMEM_BYTES);
    pv_kernel<<<dim3(8, 48), 256, PV_SMEM_BYTES>>>(out);
}